// round 3
// baseline (speedup 1.0000x reference)
#include <cuda_runtime.h>
#include <cuda_bf16.h>
#include <cstdint>
#include <cstddef>

#define VOCABN 50257
#define EMBN   256
#define HIDN   256
#define NBATCH 64
#define SEQT   2048
#define G3     768            // 3 * HID
#define ROWU   132            // uints per smem weight row (528 B stride)

// 154 MB scratch: E'[v][j] = emb[v] . W_ih[j] + b_ih[j]
__device__ float g_Ep[(size_t)VOCABN * G3];

// ---------------------------------------------------------------------------
// helpers
// ---------------------------------------------------------------------------
__device__ __forceinline__ float bflo(unsigned u) { return __uint_as_float(u << 16); }
__device__ __forceinline__ float bfhi(unsigned u) { return __uint_as_float(u & 0xffff0000u); }
__device__ __forceinline__ float sigf(float x) { return __fdividef(1.f, 1.f + __expf(-x)); }
__device__ __forceinline__ float tanhfast(float x) {
    return __fdividef(2.f, 1.f + __expf(-2.f * x)) - 1.f;
}
__device__ __forceinline__ unsigned smem_u32(const void* p) {
    unsigned a;
    asm("{ .reg .u64 t; cvta.to.shared.u64 t, %1; cvt.u32.u64 %0, t; }" : "=r"(a) : "l"(p));
    return a;
}

// ---------------------------------------------------------------------------
// Phase A: E' = emb @ W_ih^T + b_ih   (fp32 register-tiled GEMM, 128x128 tile)
// ---------------------------------------------------------------------------
__global__ void __launch_bounds__(256) eprime_kernel(
    const float* __restrict__ emb, const float* __restrict__ W_ih,
    const float* __restrict__ b_ih)
{
    __shared__ float As[32][132];   // [k][m]
    __shared__ float Bs[32][132];   // [k][n]

    const int m0 = blockIdx.x * 128;
    const int n0 = blockIdx.y * 128;
    const int tid = threadIdx.x;
    const int tx = tid & 15;        // n sub
    const int ty = tid >> 4;        // m sub

    float acc[8][8];
#pragma unroll
    for (int i = 0; i < 8; i++)
#pragma unroll
        for (int j = 0; j < 8; j++) acc[i][j] = 0.f;

    const int lr = tid >> 3;        // 0..31  (row within 32-wide chunk)
    const int lk = (tid & 7) * 4;   // 0,4,..,28

    for (int kc = 0; kc < EMBN; kc += 32) {
        __syncthreads();
#pragma unroll
        for (int i = 0; i < 4; i++) {
            int row = lr + i * 32;                    // 0..127
            int gm = m0 + row; if (gm > VOCABN - 1) gm = VOCABN - 1;
            float4 va = *(const float4*)&emb[(size_t)gm * EMBN + kc + lk];
            As[lk + 0][row] = va.x; As[lk + 1][row] = va.y;
            As[lk + 2][row] = va.z; As[lk + 3][row] = va.w;
            int gn = n0 + row;                        // < 768 always
            float4 vb = *(const float4*)&W_ih[(size_t)gn * EMBN + kc + lk];
            Bs[lk + 0][row] = vb.x; Bs[lk + 1][row] = vb.y;
            Bs[lk + 2][row] = vb.z; Bs[lk + 3][row] = vb.w;
        }
        __syncthreads();
#pragma unroll
        for (int k = 0; k < 32; k++) {
            float a[8], bb[8];
            *(float4*)&a[0]  = *(const float4*)&As[k][ty * 8];
            *(float4*)&a[4]  = *(const float4*)&As[k][ty * 8 + 4];
            *(float4*)&bb[0] = *(const float4*)&Bs[k][tx * 8];
            *(float4*)&bb[4] = *(const float4*)&Bs[k][tx * 8 + 4];
#pragma unroll
            for (int i = 0; i < 8; i++)
#pragma unroll
                for (int j = 0; j < 8; j++)
                    acc[i][j] = fmaf(a[i], bb[j], acc[i][j]);
        }
    }

    float bia[8];
#pragma unroll
    for (int j = 0; j < 8; j++) bia[j] = b_ih[n0 + tx * 8 + j];
#pragma unroll
    for (int i = 0; i < 8; i++) {
        int r = m0 + ty * 8 + i;
        if (r < VOCABN) {
            float4 v0, v1;
            v0.x = acc[i][0] + bia[0]; v0.y = acc[i][1] + bia[1];
            v0.z = acc[i][2] + bia[2]; v0.w = acc[i][3] + bia[3];
            v1.x = acc[i][4] + bia[4]; v1.y = acc[i][5] + bia[5];
            v1.z = acc[i][6] + bia[6]; v1.w = acc[i][7] + bia[7];
            *(float4*)&g_Ep[(size_t)r * G3 + n0 + tx * 8]     = v0;
            *(float4*)&g_Ep[(size_t)r * G3 + n0 + tx * 8 + 4] = v1;
        }
    }
}

// ---------------------------------------------------------------------------
// Phase B: sequential scan. 1 cluster of 2 CTAs per batch element.
// Each CTA: 384 rows of W_hh (its 128 hidden units x 3 gates) in smem as bf16.
// ---------------------------------------------------------------------------
// smem layout (bytes):
//   [0, 202752)          Ws     384 rows x 132 uints (528 B stride)
//   [202752, 204800)     h_s    2 x 256 fp32 (double buffer)
//   [204800, 205312)     z_s    128 fp32
//   [205312, 205824)     d_s    128 fp32   (gh_n + b_hh_n)
//   [205824, 206336)     e_s    128 fp32   (gi_n)
//   [206336, 207872)     b_s    384 fp32   (b_hh per row)
//   [207872, 216064)     tok_s  2048 int32
#define SCAN_SMEM 216064

__global__ void __cluster_dims__(2, 1, 1) __launch_bounds__(384, 1) scan_kernel(
    const int* __restrict__ tokens, const float* __restrict__ W_hh,
    const float* __restrict__ b_hh, const float* __restrict__ W_fc,
    const float* __restrict__ b_fc, float* __restrict__ out)
{
    extern __shared__ char smem[];
    unsigned* Ws  = (unsigned*)smem;
    float*    h_s = (float*)(smem + 202752);
    float*    z_s = (float*)(smem + 204800);
    float*    d_s = (float*)(smem + 205312);
    float*    e_s = (float*)(smem + 205824);
    float*    b_s = (float*)(smem + 206336);
    int*    tok_s = (int*)  (smem + 207872);

    const int tid = threadIdx.x;
    const int b   = blockIdx.x >> 1;
    unsigned rank;
    asm("mov.u32 %0, %%cluster_ctarank;" : "=r"(rank));
    const unsigned peer = rank ^ 1u;
    const int g   = tid >> 7;             // 0=r 1=z 2=n
    const int jj  = tid & 127;            // local hidden unit
    const int gj  = (int)rank * 128 + jj; // global hidden unit
    const int row = g * 256 + gj;         // W_hh row == E' column

    // ---- init: weights fp32 -> bf16 pairs, biases, tokens, h = 0 ----
    {
        const float2* wr2 = (const float2*)(W_hh + (size_t)row * HIDN);
        unsigned* wd = Ws + tid * ROWU;
#pragma unroll 4
        for (int i = 0; i < 128; i++) {
            float2 f = wr2[i];
            __nv_bfloat162 p = __floats2bfloat162_rn(f.x, f.y);
            wd[i] = *(unsigned*)&p;
        }
    }
    b_s[tid] = b_hh[row];
    for (int i = tid; i < SEQT; i += 384) tok_s[i] = tokens[b * SEQT + i];
    for (int i = tid; i < 2 * HIDN; i += 384) h_s[i] = 0.f;
    __syncthreads();
    asm volatile("barrier.cluster.arrive.aligned;" ::: "memory");
    asm volatile("barrier.cluster.wait.aligned;"  ::: "memory");

    const uint4* w4 = (const uint4*)(Ws + tid * ROWU);
    const unsigned h_new_local = smem_u32(&h_s[0]); // buffer parity applied later
    float gi = __ldg(&g_Ep[(size_t)tok_s[0] * G3 + row]);

    for (int t = 0; t < SEQT; t++) {
        const int cur = t & 1, nxt = cur ^ 1;

        // prefetch next step's gate preactivation (independent of h)
        float gi_nxt = 0.f;
        if (t + 1 < SEQT)
            gi_nxt = __ldg(&g_Ep[(size_t)tok_s[t + 1] * G3 + row]);

        // ---- 256-wide dot: smem bf16 weights x fp32 h (broadcast) ----
        const float4* hv = (const float4*)(h_s + cur * HIDN);
        float a0 = b_s[tid], a1 = 0.f, a2 = 0.f, a3 = 0.f;
#pragma unroll
        for (int q = 0; q < 32; q++) {
            uint4  w  = w4[q];
            float4 hA = hv[2 * q];
            float4 hB = hv[2 * q + 1];
            a0 = fmaf(bflo(w.x), hA.x, a0);
            a1 = fmaf(bfhi(w.x), hA.y, a1);
            a2 = fmaf(bflo(w.y), hA.z, a2);
            a3 = fmaf(bfhi(w.y), hA.w, a3);
            a0 = fmaf(bflo(w.z), hB.x, a0);
            a1 = fmaf(bfhi(w.z), hB.y, a1);
            a2 = fmaf(bflo(w.w), hB.z, a2);
            a3 = fmaf(bfhi(w.w), hB.w, a3);
        }
        const float a = (a0 + a1) + (a2 + a3);   // gh[row] + b_hh[row]

        float r = 0.f;
        if (g == 0) {
            r = sigf(gi + a);                    // kept in register, only g0 uses it
        } else if (g == 1) {
            z_s[jj] = sigf(gi + a);
        } else {
            d_s[jj] = a;                         // gh_n + b_hh_n
            e_s[jj] = gi;                        // gi_n
        }
        __syncthreads();

        if (g == 0) {
            float z  = z_s[jj];
            float n  = tanhfast(e_s[jj] + r * d_s[jj]);
            float ho = h_s[cur * HIDN + gj];
            float hn = fmaf(z, ho - n, n);       // (1-z)*n + z*h
            h_s[nxt * HIDN + gj] = hn;
            unsigned dst = smem_u32(&h_s[nxt * HIDN + gj]);
            asm volatile(
                "{ .reg .u32 ra; mapa.shared::cluster.u32 ra, %0, %1;"
                "  st.shared::cluster.f32 [ra], %2; }"
                :: "r"(dst), "r"(peer), "f"(hn) : "memory");
        }
        asm volatile("barrier.cluster.arrive.aligned;" ::: "memory");
        asm volatile("barrier.cluster.wait.aligned;"  ::: "memory");
        gi = gi_nxt;
    }

    // ---- final FC + sigmoid: h final lives in buffer 0 (2048 is even) ----
    if (rank == 0 && tid < 64) {
        const int o = tid >> 5;                  // output 0 or 1
        const int lane = tid & 31;
        float s = 0.f;
#pragma unroll
        for (int i = 0; i < 8; i++) {
            int k = lane * 8 + i;
            s = fmaf(h_s[k], W_fc[o * HIDN + k], s);
        }
#pragma unroll
        for (int off = 16; off; off >>= 1)
            s += __shfl_xor_sync(0xffffffffu, s, off);
        if (lane == 0) out[b * 2 + o] = sigf(s + b_fc[o]);
    }
    (void)h_new_local;
}

// ---------------------------------------------------------------------------
// launch
// ---------------------------------------------------------------------------
extern "C" void kernel_launch(void* const* d_in, const int* in_sizes, int n_in,
                              void* d_out, int out_size)
{
    const int*   tokens = (const int*)  d_in[0];
    const float* emb    = (const float*)d_in[1];
    const float* W_ih   = (const float*)d_in[2];
    const float* W_hh   = (const float*)d_in[3];
    const float* b_ih   = (const float*)d_in[4];
    const float* b_hh   = (const float*)d_in[5];
    const float* W_fc   = (const float*)d_in[6];
    const float* b_fc   = (const float*)d_in[7];
    float* out = (float*)d_out;

    cudaFuncSetAttribute(scan_kernel,
                         cudaFuncAttributeMaxDynamicSharedMemorySize, SCAN_SMEM);

    dim3 gA((VOCABN + 127) / 128, G3 / 128);
    eprime_kernel<<<gA, 256>>>(emb, W_ih, b_ih);

    scan_kernel<<<2 * NBATCH, 384, SCAN_SMEM>>>(tokens, W_hh, b_hh, W_fc, b_fc, out);

    (void)in_sizes; (void)n_in; (void)out_size;
}

// round 5
// speedup vs baseline: 1.3774x; 1.3774x over previous
#include <cuda_runtime.h>
#include <cuda_bf16.h>
#include <cstdint>
#include <cstddef>

#define VOCABN 50257
#define EMBN   256
#define HIDN   256
#define NBATCH 64
#define SEQT   2048
#define G3     768            // 3 * HID
#define ROWU   68             // uints per smem weight row (272 B stride)

// 154 MB scratch: E'[v][j] = emb[v] . W_ih[j] + b_ih[j]
__device__ float g_Ep[(size_t)VOCABN * G3];

// ---------------------------------------------------------------------------
// helpers
// ---------------------------------------------------------------------------
__device__ __forceinline__ float bflo(unsigned u) { return __uint_as_float(u << 16); }
__device__ __forceinline__ float bfhi(unsigned u) { return __uint_as_float(u & 0xffff0000u); }
__device__ __forceinline__ float sigf(float x) { return __fdividef(1.f, 1.f + __expf(-x)); }
__device__ __forceinline__ float tanhfast(float x) {
    return __fdividef(2.f, 1.f + __expf(-2.f * x)) - 1.f;
}
__device__ __forceinline__ unsigned smem_u32(const void* p) {
    unsigned a;
    asm("{ .reg .u64 t; cvta.to.shared.u64 t, %1; cvt.u32.u64 %0, t; }" : "=r"(a) : "l"(p));
    return a;
}
__device__ __forceinline__ unsigned bffma2(unsigned a, unsigned b, unsigned c) {
    unsigned d;
    asm("fma.rn.bf16x2 %0, %1, %2, %3;" : "=r"(d) : "r"(a), "r"(b), "r"(c));
    return d;
}
__device__ __forceinline__ unsigned pack_bf2(float lo, float hi) {
    __nv_bfloat162 p = __floats2bfloat162_rn(lo, hi);
    return *(unsigned*)&p;
}
__device__ __forceinline__ void mbar_wait(unsigned mbar, unsigned parity) {
    asm volatile(
        "{\n\t.reg .pred P;\n\t"
        "WL_%=:\n\t"
        "mbarrier.try_wait.parity.acquire.cta.shared::cta.b64 P, [%0], %1, 0x989680;\n\t"
        "@P bra.uni WD_%=;\n\t"
        "bra.uni WL_%=;\n\t"
        "WD_%=:\n\t}"
        :: "r"(mbar), "r"(parity) : "memory");
}

// ---------------------------------------------------------------------------
// Phase A: E' = emb @ W_ih^T + b_ih   (fp32 register-tiled GEMM, 128x128 tile)
// ---------------------------------------------------------------------------
__global__ void __launch_bounds__(256) eprime_kernel(
    const float* __restrict__ emb, const float* __restrict__ W_ih,
    const float* __restrict__ b_ih)
{
    __shared__ float As[32][132];
    __shared__ float Bs[32][132];

    const int m0 = blockIdx.x * 128;
    const int n0 = blockIdx.y * 128;
    const int tid = threadIdx.x;
    const int tx = tid & 15;
    const int ty = tid >> 4;

    float acc[8][8];
#pragma unroll
    for (int i = 0; i < 8; i++)
#pragma unroll
        for (int j = 0; j < 8; j++) acc[i][j] = 0.f;

    const int lr = tid >> 3;
    const int lk = (tid & 7) * 4;

    for (int kc = 0; kc < EMBN; kc += 32) {
        __syncthreads();
#pragma unroll
        for (int i = 0; i < 4; i++) {
            int row = lr + i * 32;
            int gm = m0 + row; if (gm > VOCABN - 1) gm = VOCABN - 1;
            float4 va = *(const float4*)&emb[(size_t)gm * EMBN + kc + lk];
            As[lk + 0][row] = va.x; As[lk + 1][row] = va.y;
            As[lk + 2][row] = va.z; As[lk + 3][row] = va.w;
            int gn = n0 + row;
            float4 vb = *(const float4*)&W_ih[(size_t)gn * EMBN + kc + lk];
            Bs[lk + 0][row] = vb.x; Bs[lk + 1][row] = vb.y;
            Bs[lk + 2][row] = vb.z; Bs[lk + 3][row] = vb.w;
        }
        __syncthreads();
#pragma unroll
        for (int k = 0; k < 32; k++) {
            float a[8], bb[8];
            *(float4*)&a[0]  = *(const float4*)&As[k][ty * 8];
            *(float4*)&a[4]  = *(const float4*)&As[k][ty * 8 + 4];
            *(float4*)&bb[0] = *(const float4*)&Bs[k][tx * 8];
            *(float4*)&bb[4] = *(const float4*)&Bs[k][tx * 8 + 4];
#pragma unroll
            for (int i = 0; i < 8; i++)
#pragma unroll
                for (int j = 0; j < 8; j++)
                    acc[i][j] = fmaf(a[i], bb[j], acc[i][j]);
        }
    }

    float bia[8];
#pragma unroll
    for (int j = 0; j < 8; j++) bia[j] = b_ih[n0 + tx * 8 + j];
#pragma unroll
    for (int i = 0; i < 8; i++) {
        int r = m0 + ty * 8 + i;
        if (r < VOCABN) {
            float4 v0, v1;
            v0.x = acc[i][0] + bia[0]; v0.y = acc[i][1] + bia[1];
            v0.z = acc[i][2] + bia[2]; v0.w = acc[i][3] + bia[3];
            v1.x = acc[i][4] + bia[4]; v1.y = acc[i][5] + bia[5];
            v1.z = acc[i][6] + bia[6]; v1.w = acc[i][7] + bia[7];
            *(float4*)&g_Ep[(size_t)r * G3 + n0 + tx * 8]     = v0;
            *(float4*)&g_Ep[(size_t)r * G3 + n0 + tx * 8 + 4] = v1;
        }
    }
}

// ---------------------------------------------------------------------------
// Phase B: sequential scan. 1 cluster of 2 CTAs per batch element.
// Weights bf16x2: cols 0..127 in REGISTERS (64 uints/thread), cols 128..255
// in smem. Dot via fma.rn.bf16x2 with periodic fp32 flush. Per-step cluster
// sync via a single 256-arrival mbarrier (local + remote release arrive).
// ---------------------------------------------------------------------------
// smem layout (bytes):
//   [0,      104448)   Ws     384 rows x 68 uints (272 B stride)
//   [104448, 105472)   h_bf   2 x 256 bf16 (double buffer)
//   [105472, 105984)   z_s    128 fp32
//   [105984, 106496)   d_s    128 fp32   (gh_n + b_hh_n)
//   [106496, 107008)   e_s    128 fp32   (gi_n)
//   [107008, 115200)   tok_s  2048 int32
//   [115200, 115208)   mbar
#define SCAN_SMEM 115216

__global__ void __cluster_dims__(2, 1, 1) __launch_bounds__(384, 1) scan_kernel(
    const int* __restrict__ tokens, const float* __restrict__ W_hh,
    const float* __restrict__ b_hh, const float* __restrict__ W_fc,
    const float* __restrict__ b_fc, float* __restrict__ out)
{
    extern __shared__ char smem[];
    unsigned*       Ws   = (unsigned*)smem;
    __nv_bfloat16*  h_bf = (__nv_bfloat16*)(smem + 104448);
    float*          z_s  = (float*)(smem + 105472);
    float*          d_s  = (float*)(smem + 105984);
    float*          e_s  = (float*)(smem + 106496);
    int*            tok_s= (int*)  (smem + 107008);
    const unsigned  mbar = smem_u32(smem + 115200);

    const int tid = threadIdx.x;
    const int b   = blockIdx.x >> 1;
    unsigned rank;
    asm("mov.u32 %0, %%cluster_ctarank;" : "=r"(rank));
    const unsigned peer = rank ^ 1u;
    const int g   = tid >> 7;             // 0=r 1=z 2=n
    const int jj  = tid & 127;            // local hidden unit
    const int gj  = (int)rank * 128 + jj; // global hidden unit
    const int row = g * 256 + gj;         // W_hh row == E' column

    // ---- init: reg weights (cols 0..127), smem weights (cols 128..255) ----
    unsigned wr[64];
    {
        const float2* p = (const float2*)(W_hh + (size_t)row * HIDN);
#pragma unroll
        for (int i = 0; i < 64; i++) {
            float2 f = p[i];
            wr[i] = pack_bf2(f.x, f.y);
        }
        unsigned* wd = Ws + tid * ROWU;
#pragma unroll 4
        for (int i = 0; i < 64; i++) {
            float2 f = p[64 + i];
            wd[i] = pack_bf2(f.x, f.y);
        }
    }
    const float bb = b_hh[row];
    for (int i = tid; i < SEQT; i += 384) tok_s[i] = tokens[b * SEQT + i];
    for (int i = tid; i < 2 * HIDN; i += 384) h_bf[i] = __float2bfloat16(0.f);
    if (tid == 0) {
        asm volatile("mbarrier.init.shared.b64 [%0], %1;" :: "r"(mbar), "r"(256u) : "memory");
    }
    __syncthreads();
    asm volatile("barrier.cluster.arrive.aligned;" ::: "memory");
    asm volatile("barrier.cluster.wait.aligned;"  ::: "memory");

    const uint4* wS = (const uint4*)(Ws + tid * ROWU);
    float hreg = 0.f;                     // this thread's own h value (g0 only)
    float gi = __ldg(&g_Ep[(size_t)tok_s[0] * G3 + row]);

    for (int t = 0; t < SEQT; t++) {
        const int cur = t & 1;
        const int nxt = cur ^ 1;

        // prefetch next step's gate preactivation (independent of h)
        float gi_nxt = 0.f;
        if (t + 1 < SEQT)
            gi_nxt = __ldg(&g_Ep[(size_t)tok_s[t + 1] * G3 + row]);

        // ---- 256-wide dot: bf16x2 weights x bf16x2 h via HFMA2 ----
        const uint4* h4 = (const uint4*)(h_bf + cur * HIDN);
        float f0 = bb, f1 = 0.f, f2 = 0.f, f3 = 0.f;
        unsigned a0 = 0u, a1 = 0u, a2 = 0u, a3 = 0u;
#pragma unroll
        for (int q = 0; q < 16; q++) {           // register half: cols 0..127
            uint4 h = h4[q];
            a0 = bffma2(wr[4 * q + 0], h.x, a0);
            a1 = bffma2(wr[4 * q + 1], h.y, a1);
            a2 = bffma2(wr[4 * q + 2], h.z, a2);
            a3 = bffma2(wr[4 * q + 3], h.w, a3);
            if ((q & 7) == 7) {                   // flush every 8 products/lane
                f0 += bflo(a0); f1 += bfhi(a0); f2 += bflo(a1); f3 += bfhi(a1);
                f0 += bflo(a2); f1 += bfhi(a2); f2 += bflo(a3); f3 += bfhi(a3);
                a0 = a1 = a2 = a3 = 0u;
            }
        }
#pragma unroll
        for (int q = 0; q < 16; q++) {           // smem half: cols 128..255
            uint4 w = wS[q];
            uint4 h = h4[16 + q];
            a0 = bffma2(w.x, h.x, a0);
            a1 = bffma2(w.y, h.y, a1);
            a2 = bffma2(w.z, h.z, a2);
            a3 = bffma2(w.w, h.w, a3);
            if ((q & 7) == 7) {
                f0 += bflo(a0); f1 += bfhi(a0); f2 += bflo(a1); f3 += bfhi(a1);
                f0 += bflo(a2); f1 += bfhi(a2); f2 += bflo(a3); f3 += bfhi(a3);
                a0 = a1 = a2 = a3 = 0u;
            }
        }
        const float a = (f0 + f1) + (f2 + f3);   // gh[row] + b_hh[row]

        float r = 0.f;
        if (g == 0) {
            r = sigf(gi + a);
        } else if (g == 1) {
            z_s[jj] = sigf(gi + a);
        } else {
            d_s[jj] = a;
            e_s[jj] = gi;
        }
        __syncthreads();

        if (g == 0) {
            float z  = z_s[jj];
            float n  = tanhfast(e_s[jj] + r * d_s[jj]);
            float hn = fmaf(z, hreg - n, n);      // (1-z)*n + z*h
            hreg = hn;
            __nv_bfloat16 hb = __float2bfloat16(hn);
            unsigned short hb16 = *(unsigned short*)&hb;
            h_bf[nxt * HIDN + gj] = hb;           // local store
            unsigned dst = smem_u32(&h_bf[nxt * HIDN + gj]);
            asm volatile(
                "{ .reg .u32 ra; mapa.shared::cluster.u32 ra, %0, %1;"
                "  st.shared::cluster.u16 [ra], %2; }"
                :: "r"(dst), "r"(peer), "h"(hb16) : "memory");
            // local arrive (orders local h_bf store for local waiters)
            asm volatile("mbarrier.arrive.release.cta.shared::cta.b64 _, [%0];"
                         :: "r"(mbar) : "memory");
            // remote arrive (release.cluster orders the remote h_bf store)
            asm volatile(
                "{ .reg .u32 ra; mapa.shared::cluster.u32 ra, %0, %1;"
                "  mbarrier.arrive.release.cluster.shared::cluster.b64 _, [ra]; }"
                :: "r"(mbar), "r"(peer) : "memory");
        }
        mbar_wait(mbar, (unsigned)(t & 1));
        gi = gi_nxt;
    }

    // ---- final FC + sigmoid: h final lives in h_bf buffer 0 (2048 even) ----
    if (rank == 0 && tid < 64) {
        const int o = tid >> 5;                  // output 0 or 1
        const int lane = tid & 31;
        float s = 0.f;
#pragma unroll
        for (int i = 0; i < 8; i++) {
            int k = lane * 8 + i;
            s = fmaf(__bfloat162float(h_bf[k]), W_fc[o * HIDN + k], s);
        }
#pragma unroll
        for (int off = 16; off; off >>= 1)
            s += __shfl_xor_sync(0xffffffffu, s, off);
        if (lane == 0) out[b * 2 + o] = sigf(s + b_fc[o]);
    }
}

// ---------------------------------------------------------------------------
// launch
// ---------------------------------------------------------------------------
extern "C" void kernel_launch(void* const* d_in, const int* in_sizes, int n_in,
                              void* d_out, int out_size)
{
    const int*   tokens = (const int*)  d_in[0];
    const float* emb    = (const float*)d_in[1];
    const float* W_ih   = (const float*)d_in[2];
    const float* W_hh   = (const float*)d_in[3];
    const float* b_ih   = (const float*)d_in[4];
    const float* b_hh   = (const float*)d_in[5];
    const float* W_fc   = (const float*)d_in[6];
    const float* b_fc   = (const float*)d_in[7];
    float* out = (float*)d_out;

    cudaFuncSetAttribute(scan_kernel,
                         cudaFuncAttributeMaxDynamicSharedMemorySize, SCAN_SMEM);

    dim3 gA((VOCABN + 127) / 128, G3 / 128);
    eprime_kernel<<<gA, 256>>>(emb, W_ih, b_ih);

    scan_kernel<<<2 * NBATCH, 384, SCAN_SMEM>>>(tokens, W_hh, b_hh, W_fc, b_fc, out);

    (void)in_sizes; (void)n_in; (void)out_size;
}

// round 7
// speedup vs baseline: 1.6187x; 1.1752x over previous
#include <cuda_runtime.h>
#include <cuda_bf16.h>
#include <cstdint>
#include <cstddef>

#define VOCABN 50257
#define EMBN   256
#define HIDN   256
#define NBATCH 64
#define SEQT   2048
#define G3     768

// 154 MB scratch: E'[v][j] = emb[v] . W_ih[j] + b_ih[j]
__device__ float g_Ep[(size_t)VOCABN * G3];

// ---------------------------------------------------------------------------
// helpers
// ---------------------------------------------------------------------------
__device__ __forceinline__ float bflo(unsigned u) { return __uint_as_float(u << 16); }
__device__ __forceinline__ float bfhi(unsigned u) { return __uint_as_float(u & 0xffff0000u); }
__device__ __forceinline__ float sigf(float x) { return __fdividef(1.f, 1.f + __expf(-x)); }
__device__ __forceinline__ float tanhfast(float x) {
    return __fdividef(2.f, 1.f + __expf(-2.f * x)) - 1.f;
}
__device__ __forceinline__ unsigned smem_u32(const void* p) {
    unsigned a;
    asm("{ .reg .u64 t; cvta.to.shared.u64 t, %1; cvt.u32.u64 %0, t; }" : "=r"(a) : "l"(p));
    return a;
}
__device__ __forceinline__ unsigned bffma2(unsigned a, unsigned b, unsigned c) {
    unsigned d;
    asm("fma.rn.bf16x2 %0, %1, %2, %3;" : "=r"(d) : "r"(a), "r"(b), "r"(c));
    return d;
}
__device__ __forceinline__ unsigned pack_bf2(float lo, float hi) {
    __nv_bfloat162 p = __floats2bfloat162_rn(lo, hi);
    return *(unsigned*)&p;
}
__device__ __forceinline__ void mbar_wait(unsigned mbar, unsigned parity) {
    asm volatile(
        "{\n\t.reg .pred P;\n\t"
        "WL_%=:\n\t"
        "mbarrier.try_wait.parity.acquire.cta.shared::cta.b64 P, [%0], %1, 0x989680;\n\t"
        "@P bra.uni WD_%=;\n\t"
        "bra.uni WL_%=;\n\t"
        "WD_%=:\n\t}"
        :: "r"(mbar), "r"(parity) : "memory");
}

// ---------------------------------------------------------------------------
// Phase A: E' = emb @ W_ih^T + b_ih   (fp32 register-tiled GEMM, 128x128 tile)
// ---------------------------------------------------------------------------
__global__ void __launch_bounds__(256) eprime_kernel(
    const float* __restrict__ emb, const float* __restrict__ W_ih,
    const float* __restrict__ b_ih)
{
    __shared__ float As[32][132];
    __shared__ float Bs[32][132];

    const int m0 = blockIdx.x * 128;
    const int n0 = blockIdx.y * 128;
    const int tid = threadIdx.x;
    const int tx = tid & 15;
    const int ty = tid >> 4;

    float acc[8][8];
#pragma unroll
    for (int i = 0; i < 8; i++)
#pragma unroll
        for (int j = 0; j < 8; j++) acc[i][j] = 0.f;

    const int lr = tid >> 3;
    const int lk = (tid & 7) * 4;

    for (int kc = 0; kc < EMBN; kc += 32) {
        __syncthreads();
#pragma unroll
        for (int i = 0; i < 4; i++) {
            int row = lr + i * 32;
            int gm = m0 + row; if (gm > VOCABN - 1) gm = VOCABN - 1;
            float4 va = *(const float4*)&emb[(size_t)gm * EMBN + kc + lk];
            As[lk + 0][row] = va.x; As[lk + 1][row] = va.y;
            As[lk + 2][row] = va.z; As[lk + 3][row] = va.w;
            int gn = n0 + row;
            float4 vb = *(const float4*)&W_ih[(size_t)gn * EMBN + kc + lk];
            Bs[lk + 0][row] = vb.x; Bs[lk + 1][row] = vb.y;
            Bs[lk + 2][row] = vb.z; Bs[lk + 3][row] = vb.w;
        }
        __syncthreads();
#pragma unroll
        for (int k = 0; k < 32; k++) {
            float a[8], bb[8];
            *(float4*)&a[0]  = *(const float4*)&As[k][ty * 8];
            *(float4*)&a[4]  = *(const float4*)&As[k][ty * 8 + 4];
            *(float4*)&bb[0] = *(const float4*)&Bs[k][tx * 8];
            *(float4*)&bb[4] = *(const float4*)&Bs[k][tx * 8 + 4];
#pragma unroll
            for (int i = 0; i < 8; i++)
#pragma unroll
                for (int j = 0; j < 8; j++)
                    acc[i][j] = fmaf(a[i], bb[j], acc[i][j]);
        }
    }

    float bia[8];
#pragma unroll
    for (int j = 0; j < 8; j++) bia[j] = b_ih[n0 + tx * 8 + j];
#pragma unroll
    for (int i = 0; i < 8; i++) {
        int r = m0 + ty * 8 + i;
        if (r < VOCABN) {
            float4 v0, v1;
            v0.x = acc[i][0] + bia[0]; v0.y = acc[i][1] + bia[1];
            v0.z = acc[i][2] + bia[2]; v0.w = acc[i][3] + bia[3];
            v1.x = acc[i][4] + bia[4]; v1.y = acc[i][5] + bia[5];
            v1.z = acc[i][6] + bia[6]; v1.w = acc[i][7] + bia[7];
            *(float4*)&g_Ep[(size_t)r * G3 + n0 + tx * 8]     = v0;
            *(float4*)&g_Ep[(size_t)r * G3 + n0 + tx * 8 + 4] = v1;
        }
    }
}

// ---------------------------------------------------------------------------
// Phase B: scan. Cluster of 2 CTAs per batch element, 512 threads/CTA.
// Thread = (unit jj = tid>>2, quarter q4 = tid&3): computes all 3 gate dots
// over cols [q4*64, q4*64+64). r,z weights in regs; n weights in smem.
// 4-way shfl reduce -> every thread has full r,z,n sums -> local epilogue.
// Per-step sync: h exchange + one 256-arrival mbarrier (local+remote arrive).
// Race-safety without __syncthreads: each writer's arrive is ordered after
// its warp's shfl_xor_sync (full-warp sync, after the dot reads); wait needs
// arrivals from all 32 warps of the cluster, so passing wait(t-1) implies all
// warps finished their step t-1 reads before anyone writes that buffer at t.
// ---------------------------------------------------------------------------
// smem layout (bytes):
//   [0,     73728)  Wn     512 threads x 32 uints @ 144 B stride (36 uints)
//   [73728, 74880)  h_bf   2 buffers x 4 col-blocks x 144 B (64 bf16 + pad)
//   [74880, 83072)  tok_s  2048 int32
//   [83072, 83080)  mbar
#define SCAN_SMEM 83088
#define HBUF_STRIDE 576   // bytes per h buffer (4 blocks x 144)

__global__ void __cluster_dims__(2, 1, 1) __launch_bounds__(512, 1) scan_kernel(
    const int* __restrict__ tokens, const float* __restrict__ W_hh,
    const float* __restrict__ b_hh, const float* __restrict__ W_fc,
    const float* __restrict__ b_fc, float* __restrict__ out)
{
    extern __shared__ char smem[];
    unsigned* Wn    = (unsigned*)smem;
    char*     h_raw = smem + 73728;
    int*      tok_s = (int*)(smem + 74880);
    const unsigned mbar = smem_u32(smem + 83072);

    const int tid = threadIdx.x;
    const int b   = blockIdx.x >> 1;
    unsigned rank;
    asm("mov.u32 %0, %%cluster_ctarank;" : "=r"(rank));
    const unsigned peer = rank ^ 1u;
    const int jj = tid >> 2;              // local hidden unit 0..127
    const int q4 = tid & 3;               // column quarter
    const int gj = (int)rank * 128 + jj;  // global hidden unit
    const int c0 = q4 * 64;               // first column of this quarter

    // ---- init: weights. r,z gates -> regs; n gate -> smem ----
    unsigned wr_r[32], wr_z[32];
    {
        const float2* pr = (const float2*)(W_hh + (size_t)(gj)       * HIDN + c0);
        const float2* pz = (const float2*)(W_hh + (size_t)(256 + gj) * HIDN + c0);
        const float2* pn = (const float2*)(W_hh + (size_t)(512 + gj) * HIDN + c0);
        unsigned* wd = Wn + tid * 36;
#pragma unroll
        for (int i = 0; i < 32; i++) {
            float2 fr = pr[i]; wr_r[i] = pack_bf2(fr.x, fr.y);
            float2 fz = pz[i]; wr_z[i] = pack_bf2(fz.x, fz.y);
            float2 fn = pn[i]; wd[i]   = pack_bf2(fn.x, fn.y);
        }
    }
    const float bhr = b_hh[gj];
    const float bhz = b_hh[256 + gj];
    const float bhn = b_hh[512 + gj];

    for (int i = tid; i < SEQT; i += 512) tok_s[i] = tokens[b * SEQT + i];
    for (int i = tid; i < 2 * HBUF_STRIDE / 4; i += 512) ((unsigned*)h_raw)[i] = 0u;
    if (tid == 0) {
        asm volatile("mbarrier.init.shared.b64 [%0], %1;" :: "r"(mbar), "r"(256u) : "memory");
    }
    __syncthreads();
    asm volatile("barrier.cluster.arrive.aligned;" ::: "memory");
    asm volatile("barrier.cluster.wait.aligned;"  ::: "memory");

    const uint4* wn4 = (const uint4*)(Wn + tid * 36);
    const int hoff = (gj >> 6) * 144 + (gj & 63) * 2;   // this unit's h slot
    float hreg = 0.f;

    // gi preactivations for t=0
    const float* ep0 = &g_Ep[(size_t)tok_s[0] * G3];
    float gir = __ldg(ep0 + gj), giz = __ldg(ep0 + 256 + gj), gin = __ldg(ep0 + 512 + gj);

    for (int t = 0; t < SEQT; t++) {
        const int cur = t & 1;
        const int nxt = cur ^ 1;

        // prefetch next step's preactivations (independent of h)
        const int tn = (t + 1 < SEQT) ? tok_s[t + 1] : tok_s[t];
        const float* epn = &g_Ep[(size_t)tn * G3];
        float girn = __ldg(epn + gj);
        float gizn = __ldg(epn + 256 + gj);
        float ginn = __ldg(epn + 512 + gj);

        // ---- 3 gate dots over this quarter's 64 cols (32 bf16x2) ----
        const uint4* h4 = (const uint4*)(h_raw + cur * HBUF_STRIDE + q4 * 144);
        unsigned ar0 = 0u, ar1 = 0u, az0 = 0u, az1 = 0u, an0 = 0u, an1 = 0u;
#pragma unroll
        for (int k = 0; k < 8; k++) {
            uint4 h = h4[k];
            uint4 w = wn4[k];
            ar0 = bffma2(wr_r[4 * k + 0], h.x, ar0);
            ar1 = bffma2(wr_r[4 * k + 1], h.y, ar1);
            az0 = bffma2(wr_z[4 * k + 0], h.x, az0);
            az1 = bffma2(wr_z[4 * k + 1], h.y, az1);
            an0 = bffma2(w.x, h.x, an0);
            an1 = bffma2(w.y, h.y, an1);
            ar0 = bffma2(wr_r[4 * k + 2], h.z, ar0);
            ar1 = bffma2(wr_r[4 * k + 3], h.w, ar1);
            az0 = bffma2(wr_z[4 * k + 2], h.z, az0);
            az1 = bffma2(wr_z[4 * k + 3], h.w, az1);
            an0 = bffma2(w.z, h.z, an0);
            an1 = bffma2(w.w, h.w, an1);
        }
        float sr = (bflo(ar0) + bfhi(ar0)) + (bflo(ar1) + bfhi(ar1));
        float sz = (bflo(az0) + bfhi(az0)) + (bflo(az1) + bfhi(az1));
        float sn = (bflo(an0) + bfhi(an0)) + (bflo(an1) + bfhi(an1));

        // 4-way reduce across the quarter group (lanes xor 1, xor 2)
        sr += __shfl_xor_sync(0xffffffffu, sr, 1);
        sz += __shfl_xor_sync(0xffffffffu, sz, 1);
        sn += __shfl_xor_sync(0xffffffffu, sn, 1);
        sr += __shfl_xor_sync(0xffffffffu, sr, 2);
        sz += __shfl_xor_sync(0xffffffffu, sz, 2);
        sn += __shfl_xor_sync(0xffffffffu, sn, 2);

        // ---- epilogue (all 4 threads redundantly; q4==0 stores) ----
        float r  = sigf(gir + bhr + sr);
        float z  = sigf(giz + bhz + sz);
        float n  = tanhfast(gin + r * (sn + bhn));
        float hn = fmaf(z, hreg - n, n);        // (1-z)*n + z*h
        hreg = hn;

        if (q4 == 0) {
            __nv_bfloat16 hb = __float2bfloat16(hn);
            unsigned short hb16 = *(unsigned short*)&hb;
            char* dstp = h_raw + nxt * HBUF_STRIDE + hoff;
            *(__nv_bfloat16*)dstp = hb;          // local store
            unsigned dst = smem_u32(dstp);
            asm volatile(
                "{ .reg .u32 ra; mapa.shared::cluster.u32 ra, %0, %1;"
                "  st.shared::cluster.u16 [ra], %2; }"
                :: "r"(dst), "r"(peer), "h"(hb16) : "memory");
            asm volatile("mbarrier.arrive.release.cta.shared::cta.b64 _, [%0];"
                         :: "r"(mbar) : "memory");
            asm volatile(
                "{ .reg .u32 ra; mapa.shared::cluster.u32 ra, %0, %1;"
                "  mbarrier.arrive.release.cluster.shared::cluster.b64 _, [ra]; }"
                :: "r"(mbar), "r"(peer) : "memory");
        }
        mbar_wait(mbar, (unsigned)(t & 1));
        gir = girn; giz = gizn; gin = ginn;
    }

    // ---- final FC + sigmoid: final h lives in buffer 0 (2048 even) ----
    if (rank == 0 && tid < 64) {
        const int o = tid >> 5;
        const int lane = tid & 31;
        float s = 0.f;
#pragma unroll
        for (int i = 0; i < 8; i++) {
            int k = lane * 8 + i;
            const __nv_bfloat16* hp =
                (const __nv_bfloat16*)(h_raw + (k >> 6) * 144 + (k & 63) * 2);
            s = fmaf(__bfloat162float(*hp), W_fc[o * HIDN + k], s);
        }
#pragma unroll
        for (int off = 16; off; off >>= 1)
            s += __shfl_xor_sync(0xffffffffu, s, off);
        if (lane == 0) out[b * 2 + o] = sigf(s + b_fc[o]);
    }
}

// ---------------------------------------------------------------------------
// launch
// ---------------------------------------------------------------------------
extern "C" void kernel_launch(void* const* d_in, const int* in_sizes, int n_in,
                              void* d_out, int out_size)
{
    const int*   tokens = (const int*)  d_in[0];
    const float* emb    = (const float*)d_in[1];
    const float* W_ih   = (const float*)d_in[2];
    const float* W_hh   = (const float*)d_in[3];
    const float* b_ih   = (const float*)d_in[4];
    const float* b_hh   = (const float*)d_in[5];
    const float* W_fc   = (const float*)d_in[6];
    const float* b_fc   = (const float*)d_in[7];
    float* out = (float*)d_out;

    cudaFuncSetAttribute(scan_kernel,
                         cudaFuncAttributeMaxDynamicSharedMemorySize, SCAN_SMEM);

    dim3 gA((VOCABN + 127) / 128, G3 / 128);
    eprime_kernel<<<gA, 256>>>(emb, W_ih, b_ih);

    scan_kernel<<<2 * NBATCH, 512, SCAN_SMEM>>>(tokens, W_hh, b_hh, W_fc, b_fc, out);

    (void)in_sizes; (void)n_in; (void)out_size;
}

// round 8
// speedup vs baseline: 1.7529x; 1.0828x over previous
#include <cuda_runtime.h>
#include <cuda_bf16.h>
#include <cstdint>
#include <cstddef>

#define VOCABN 50257
#define EMBN   256
#define HIDN   256
#define NBATCH 64
#define SEQT   2048
#define G3     768

// 154 MB scratch: E'[v][j] = emb[v] . W_ih[j] + b_ih[j]
__device__ float g_Ep[(size_t)VOCABN * G3];

// ---------------------------------------------------------------------------
// helpers
// ---------------------------------------------------------------------------
__device__ __forceinline__ float bflo(unsigned u) { return __uint_as_float(u << 16); }
__device__ __forceinline__ float bfhi(unsigned u) { return __uint_as_float(u & 0xffff0000u); }
__device__ __forceinline__ float tanhapx(float x) {
    float y;
    asm("tanh.approx.f32 %0, %1;" : "=f"(y) : "f"(x));
    return y;
}
// sigmoid(x) = 0.5 + 0.5 * tanh(0.5 x)
__device__ __forceinline__ float sigapx(float x) {
    return fmaf(0.5f, tanhapx(0.5f * x), 0.5f);
}
__device__ __forceinline__ unsigned smem_u32(const void* p) {
    unsigned a;
    asm("{ .reg .u64 t; cvta.to.shared.u64 t, %1; cvt.u32.u64 %0, t; }" : "=r"(a) : "l"(p));
    return a;
}
__device__ __forceinline__ unsigned bffma2(unsigned a, unsigned b, unsigned c) {
    unsigned d;
    asm("fma.rn.bf16x2 %0, %1, %2, %3;" : "=r"(d) : "r"(a), "r"(b), "r"(c));
    return d;
}
__device__ __forceinline__ unsigned pack_bf2(float lo, float hi) {
    __nv_bfloat162 p = __floats2bfloat162_rn(lo, hi);
    return *(unsigned*)&p;
}
__device__ __forceinline__ void mbar_wait(unsigned mbar, unsigned parity) {
    asm volatile(
        "{\n\t.reg .pred P;\n\t"
        "WL_%=:\n\t"
        "mbarrier.try_wait.parity.acquire.cta.shared::cta.b64 P, [%0], %1, 0x989680;\n\t"
        "@P bra.uni WD_%=;\n\t"
        "bra.uni WL_%=;\n\t"
        "WD_%=:\n\t}"
        :: "r"(mbar), "r"(parity) : "memory");
}

// ---------------------------------------------------------------------------
// Phase A: E' = emb @ W_ih^T + b_ih   (fp32 register-tiled GEMM, 128x128 tile)
// ---------------------------------------------------------------------------
__global__ void __launch_bounds__(256) eprime_kernel(
    const float* __restrict__ emb, const float* __restrict__ W_ih,
    const float* __restrict__ b_ih)
{
    __shared__ float As[32][132];
    __shared__ float Bs[32][132];

    const int m0 = blockIdx.x * 128;
    const int n0 = blockIdx.y * 128;
    const int tid = threadIdx.x;
    const int tx = tid & 15;
    const int ty = tid >> 4;

    float acc[8][8];
#pragma unroll
    for (int i = 0; i < 8; i++)
#pragma unroll
        for (int j = 0; j < 8; j++) acc[i][j] = 0.f;

    const int lr = tid >> 3;
    const int lk = (tid & 7) * 4;

    for (int kc = 0; kc < EMBN; kc += 32) {
        __syncthreads();
#pragma unroll
        for (int i = 0; i < 4; i++) {
            int row = lr + i * 32;
            int gm = m0 + row; if (gm > VOCABN - 1) gm = VOCABN - 1;
            float4 va = *(const float4*)&emb[(size_t)gm * EMBN + kc + lk];
            As[lk + 0][row] = va.x; As[lk + 1][row] = va.y;
            As[lk + 2][row] = va.z; As[lk + 3][row] = va.w;
            int gn = n0 + row;
            float4 vb = *(const float4*)&W_ih[(size_t)gn * EMBN + kc + lk];
            Bs[lk + 0][row] = vb.x; Bs[lk + 1][row] = vb.y;
            Bs[lk + 2][row] = vb.z; Bs[lk + 3][row] = vb.w;
        }
        __syncthreads();
#pragma unroll
        for (int k = 0; k < 32; k++) {
            float a[8], bb[8];
            *(float4*)&a[0]  = *(const float4*)&As[k][ty * 8];
            *(float4*)&a[4]  = *(const float4*)&As[k][ty * 8 + 4];
            *(float4*)&bb[0] = *(const float4*)&Bs[k][tx * 8];
            *(float4*)&bb[4] = *(const float4*)&Bs[k][tx * 8 + 4];
#pragma unroll
            for (int i = 0; i < 8; i++)
#pragma unroll
                for (int j = 0; j < 8; j++)
                    acc[i][j] = fmaf(a[i], bb[j], acc[i][j]);
        }
    }

    float bia[8];
#pragma unroll
    for (int j = 0; j < 8; j++) bia[j] = b_ih[n0 + tx * 8 + j];
#pragma unroll
    for (int i = 0; i < 8; i++) {
        int r = m0 + ty * 8 + i;
        if (r < VOCABN) {
            float4 v0, v1;
            v0.x = acc[i][0] + bia[0]; v0.y = acc[i][1] + bia[1];
            v0.z = acc[i][2] + bia[2]; v0.w = acc[i][3] + bia[3];
            v1.x = acc[i][4] + bia[4]; v1.y = acc[i][5] + bia[5];
            v1.z = acc[i][6] + bia[6]; v1.w = acc[i][7] + bia[7];
            *(float4*)&g_Ep[(size_t)r * G3 + n0 + tx * 8]     = v0;
            *(float4*)&g_Ep[(size_t)r * G3 + n0 + tx * 8 + 4] = v1;
        }
    }
}

// ---------------------------------------------------------------------------
// Phase B: scan. Cluster of 2 CTAs per batch element, 512 threads/CTA.
// Thread = (unit jj = tid>>2, quarter q4 = tid&3): all 3 gate dots over cols
// [q4*64, q4*64+64). Weights: r(32u), z(32u), n-first-half(16u) in REGISTERS
// (80 uints); n-second-half(16u) in smem @ 80 B stride (conflict-free).
// 4-way shfl reduce -> local epilogue with tanh.approx -> q4==0 stores h.
// Per-step sync: one 256-arrival mbarrier (local + remote release arrive).
// Race-safety without __syncthreads: writer's arrive is ordered after its
// warp's shfl_xor_sync (full-warp sync after the dot reads); the wait needs
// arrivals from all 32 warps of the cluster.
// ---------------------------------------------------------------------------
// smem layout (bytes):
//   [0,     40960)  Wn2    512 threads x 16 uints @ 80 B stride (20 uints)
//   [40960, 42112)  h_bf   2 buffers x 4 col-blocks x 144 B (64 bf16 + pad)
//   [42112, 50304)  tok_s  2048 int32
//   [50304, 50312)  mbar
#define SCAN_SMEM 50320
#define HBUF_STRIDE 576   // bytes per h buffer (4 blocks x 144)

__global__ void __cluster_dims__(2, 1, 1) __launch_bounds__(512, 1) scan_kernel(
    const int* __restrict__ tokens, const float* __restrict__ W_hh,
    const float* __restrict__ b_hh, const float* __restrict__ W_fc,
    const float* __restrict__ b_fc, float* __restrict__ out)
{
    extern __shared__ char smem[];
    unsigned* Wn2   = (unsigned*)smem;
    char*     h_raw = smem + 40960;
    int*      tok_s = (int*)(smem + 42112);
    const unsigned mbar = smem_u32(smem + 50304);

    const int tid = threadIdx.x;
    const int b   = blockIdx.x >> 1;
    unsigned rank;
    asm("mov.u32 %0, %%cluster_ctarank;" : "=r"(rank));
    const unsigned peer = rank ^ 1u;
    const int jj = tid >> 2;              // local hidden unit 0..127
    const int q4 = tid & 3;               // column quarter
    const int gj = (int)rank * 128 + jj;  // global hidden unit
    const int c0 = q4 * 64;               // first column of this quarter

    // ---- init: weights. r,z + first half of n -> regs; rest of n -> smem --
    unsigned wr_r[32], wr_z[32], wr_n[16];
    {
        const float2* pr = (const float2*)(W_hh + (size_t)(gj)       * HIDN + c0);
        const float2* pz = (const float2*)(W_hh + (size_t)(256 + gj) * HIDN + c0);
        const float2* pn = (const float2*)(W_hh + (size_t)(512 + gj) * HIDN + c0);
        unsigned* wd = Wn2 + tid * 20;
#pragma unroll
        for (int i = 0; i < 32; i++) {
            float2 fr = pr[i]; wr_r[i] = pack_bf2(fr.x, fr.y);
            float2 fz = pz[i]; wr_z[i] = pack_bf2(fz.x, fz.y);
        }
#pragma unroll
        for (int i = 0; i < 16; i++) {
            float2 fa = pn[i];      wr_n[i] = pack_bf2(fa.x, fa.y);
            float2 fb = pn[16 + i]; wd[i]   = pack_bf2(fb.x, fb.y);
        }
    }
    const float bhr = b_hh[gj];
    const float bhz = b_hh[256 + gj];
    const float bhn = b_hh[512 + gj];

    for (int i = tid; i < SEQT; i += 512) tok_s[i] = tokens[b * SEQT + i];
    for (int i = tid; i < 2 * HBUF_STRIDE / 4; i += 512) ((unsigned*)h_raw)[i] = 0u;
    if (tid == 0) {
        asm volatile("mbarrier.init.shared.b64 [%0], %1;" :: "r"(mbar), "r"(256u) : "memory");
    }
    __syncthreads();
    asm volatile("barrier.cluster.arrive.aligned;" ::: "memory");
    asm volatile("barrier.cluster.wait.aligned;"  ::: "memory");

    const uint4* wn4 = (const uint4*)(Wn2 + tid * 20);
    const int hoff = (gj >> 6) * 144 + (gj & 63) * 2;   // this unit's h slot
    float hreg = 0.f;

    // gi preactivations for t=0 (biases folded in)
    const float* ep0 = &g_Ep[(size_t)tok_s[0] * G3];
    float gir = __ldg(ep0 + gj)       + bhr;
    float giz = __ldg(ep0 + 256 + gj) + bhz;
    float gin = __ldg(ep0 + 512 + gj);

    for (int t = 0; t < SEQT; t++) {
        const int cur = t & 1;
        const int nxt = cur ^ 1;

        // prefetch next step's preactivations (independent of h)
        const int tn = (t + 1 < SEQT) ? tok_s[t + 1] : tok_s[t];
        const float* epn = &g_Ep[(size_t)tn * G3];
        float girn = __ldg(epn + gj);
        float gizn = __ldg(epn + 256 + gj);
        float ginn = __ldg(epn + 512 + gj);

        // ---- 3 gate dots over this quarter's 64 cols (32 bf16x2) ----
        const uint4* h4 = (const uint4*)(h_raw + cur * HBUF_STRIDE + q4 * 144);
        unsigned ar0 = 0u, ar1 = 0u, az0 = 0u, az1 = 0u, an0 = 0u, an1 = 0u;
#pragma unroll
        for (int k = 0; k < 4; k++) {            // cols 0..31: n from regs
            uint4 h = h4[k];
            ar0 = bffma2(wr_r[4 * k + 0], h.x, ar0);
            ar1 = bffma2(wr_r[4 * k + 1], h.y, ar1);
            az0 = bffma2(wr_z[4 * k + 0], h.x, az0);
            az1 = bffma2(wr_z[4 * k + 1], h.y, az1);
            an0 = bffma2(wr_n[4 * k + 0], h.x, an0);
            an1 = bffma2(wr_n[4 * k + 1], h.y, an1);
            ar0 = bffma2(wr_r[4 * k + 2], h.z, ar0);
            ar1 = bffma2(wr_r[4 * k + 3], h.w, ar1);
            az0 = bffma2(wr_z[4 * k + 2], h.z, az0);
            az1 = bffma2(wr_z[4 * k + 3], h.w, az1);
            an0 = bffma2(wr_n[4 * k + 2], h.z, an0);
            an1 = bffma2(wr_n[4 * k + 3], h.w, an1);
        }
#pragma unroll
        for (int k = 4; k < 8; k++) {            // cols 32..63: n from smem
            uint4 h = h4[k];
            uint4 w = wn4[k - 4];
            ar0 = bffma2(wr_r[4 * k + 0], h.x, ar0);
            ar1 = bffma2(wr_r[4 * k + 1], h.y, ar1);
            az0 = bffma2(wr_z[4 * k + 0], h.x, az0);
            az1 = bffma2(wr_z[4 * k + 1], h.y, az1);
            an0 = bffma2(w.x, h.x, an0);
            an1 = bffma2(w.y, h.y, an1);
            ar0 = bffma2(wr_r[4 * k + 2], h.z, ar0);
            ar1 = bffma2(wr_r[4 * k + 3], h.w, ar1);
            az0 = bffma2(wr_z[4 * k + 2], h.z, az0);
            az1 = bffma2(wr_z[4 * k + 3], h.w, az1);
            an0 = bffma2(w.z, h.z, an0);
            an1 = bffma2(w.w, h.w, an1);
        }
        float sr = (bflo(ar0) + bfhi(ar0)) + (bflo(ar1) + bfhi(ar1));
        float sz = (bflo(az0) + bfhi(az0)) + (bflo(az1) + bfhi(az1));
        float sn = (bflo(an0) + bfhi(an0)) + (bflo(an1) + bfhi(an1));

        // 4-way reduce across the quarter group (lanes xor 1, xor 2)
        sr += __shfl_xor_sync(0xffffffffu, sr, 1);
        sz += __shfl_xor_sync(0xffffffffu, sz, 1);
        sn += __shfl_xor_sync(0xffffffffu, sn, 1);
        sr += __shfl_xor_sync(0xffffffffu, sr, 2);
        sz += __shfl_xor_sync(0xffffffffu, sz, 2);
        sn += __shfl_xor_sync(0xffffffffu, sn, 2);

        // ---- epilogue (all 4 threads redundantly; q4==0 stores) ----
        float r  = sigapx(gir + sr);
        float z  = sigapx(giz + sz);
        float n  = tanhapx(gin + r * (sn + bhn));
        float hn = fmaf(z, hreg - n, n);        // (1-z)*n + z*h
        hreg = hn;

        if (q4 == 0) {
            __nv_bfloat16 hb = __float2bfloat16(hn);
            unsigned short hb16 = *(unsigned short*)&hb;
            char* dstp = h_raw + nxt * HBUF_STRIDE + hoff;
            *(__nv_bfloat16*)dstp = hb;          // local store
            unsigned dst = smem_u32(dstp);
            asm volatile(
                "{ .reg .u32 ra; mapa.shared::cluster.u32 ra, %0, %1;"
                "  st.shared::cluster.u16 [ra], %2; }"
                :: "r"(dst), "r"(peer), "h"(hb16) : "memory");
            asm volatile("mbarrier.arrive.release.cta.shared::cta.b64 _, [%0];"
                         :: "r"(mbar) : "memory");
            asm volatile(
                "{ .reg .u32 ra; mapa.shared::cluster.u32 ra, %0, %1;"
                "  mbarrier.arrive.release.cluster.shared::cluster.b64 _, [ra]; }"
                :: "r"(mbar), "r"(peer) : "memory");
        }
        mbar_wait(mbar, (unsigned)(t & 1));
        gir = girn + bhr;
        giz = gizn + bhz;
        gin = ginn;
    }

    // ---- final FC + sigmoid: final h lives in buffer 0 (2048 even) ----
    if (rank == 0 && tid < 64) {
        const int o = tid >> 5;
        const int lane = tid & 31;
        float s = 0.f;
#pragma unroll
        for (int i = 0; i < 8; i++) {
            int k = lane * 8 + i;
            const __nv_bfloat16* hp =
                (const __nv_bfloat16*)(h_raw + (k >> 6) * 144 + (k & 63) * 2);
            s = fmaf(__bfloat162float(*hp), W_fc[o * HIDN + k], s);
        }
#pragma unroll
        for (int off = 16; off; off >>= 1)
            s += __shfl_xor_sync(0xffffffffu, s, off);
        // exact sigmoid here (final output precision matters most)
        if (lane == 0) out[b * 2 + o] = __fdividef(1.f, 1.f + __expf(-(s + b_fc[o])));
    }
}

// ---------------------------------------------------------------------------
// launch
// ---------------------------------------------------------------------------
extern "C" void kernel_launch(void* const* d_in, const int* in_sizes, int n_in,
                              void* d_out, int out_size)
{
    const int*   tokens = (const int*)  d_in[0];
    const float* emb    = (const float*)d_in[1];
    const float* W_ih   = (const float*)d_in[2];
    const float* W_hh   = (const float*)d_in[3];
    const float* b_ih   = (const float*)d_in[4];
    const float* b_hh   = (const float*)d_in[5];
    const float* W_fc   = (const float*)d_in[6];
    const float* b_fc   = (const float*)d_in[7];
    float* out = (float*)d_out;

    cudaFuncSetAttribute(scan_kernel,
                         cudaFuncAttributeMaxDynamicSharedMemorySize, SCAN_SMEM);

    dim3 gA((VOCABN + 127) / 128, G3 / 128);
    eprime_kernel<<<gA, 256>>>(emb, W_ih, b_ih);

    scan_kernel<<<2 * NBATCH, 512, SCAN_SMEM>>>(tokens, W_hh, b_hh, W_fc, b_fc, out);

    (void)in_sizes; (void)n_in; (void)out_size;
}

// round 9
// speedup vs baseline: 1.8600x; 1.0611x over previous
#include <cuda_runtime.h>
#include <cuda_bf16.h>
#include <cstdint>
#include <cstddef>

#define VOCABN 50257
#define EMBN   256
#define HIDN   256
#define NBATCH 64
#define SEQT   2048
#define G3     768

// 154 MB scratch: E'[v][j] = emb[v] . W_ih[j] + b_ih[j]
__device__ float g_Ep[(size_t)VOCABN * G3];

typedef unsigned long long ull;

// ---------------------------------------------------------------------------
// helpers
// ---------------------------------------------------------------------------
__device__ __forceinline__ float bflo(unsigned u) { return __uint_as_float(u << 16); }
__device__ __forceinline__ float bfhi(unsigned u) { return __uint_as_float(u & 0xffff0000u); }
__device__ __forceinline__ float tanhapx(float x) {
    float y;
    asm("tanh.approx.f32 %0, %1;" : "=f"(y) : "f"(x));
    return y;
}
__device__ __forceinline__ float sigapx(float x) {   // 0.5 + 0.5*tanh(x/2)
    return fmaf(0.5f, tanhapx(0.5f * x), 0.5f);
}
__device__ __forceinline__ unsigned smem_u32(const void* p) {
    unsigned a;
    asm("{ .reg .u64 t; cvta.to.shared.u64 t, %1; cvt.u32.u64 %0, t; }" : "=r"(a) : "l"(p));
    return a;
}
__device__ __forceinline__ unsigned bffma2(unsigned a, unsigned b, unsigned c) {
    unsigned d;
    asm("fma.rn.bf16x2 %0, %1, %2, %3;" : "=r"(d) : "r"(a), "r"(b), "r"(c));
    return d;
}
__device__ __forceinline__ unsigned pack_bf2(float lo, float hi) {
    __nv_bfloat162 p = __floats2bfloat162_rn(lo, hi);
    return *(unsigned*)&p;
}
__device__ __forceinline__ ull f32x2fma(ull a, ull b, ull c) {
    ull d;
    asm("fma.rn.f32x2 %0, %1, %2, %3;" : "=l"(d) : "l"(a), "l"(b), "l"(c));
    return d;
}
__device__ __forceinline__ ull dup2(float x) {
    ull d;
    asm("mov.b64 %0, {%1, %1};" : "=l"(d) : "f"(x));
    return d;
}
__device__ __forceinline__ ull pk2(float lo, float hi) {
    ull d;
    asm("mov.b64 %0, {%1, %2};" : "=l"(d) : "f"(lo), "f"(hi));
    return d;
}
__device__ __forceinline__ void upk2(ull v, float& lo, float& hi) {
    asm("mov.b64 {%0, %1}, %2;" : "=f"(lo), "=f"(hi) : "l"(v));
}
__device__ __forceinline__ void mbar_wait(unsigned mbar, unsigned parity) {
    asm volatile(
        "{\n\t.reg .pred P;\n\t"
        "WL_%=:\n\t"
        "mbarrier.try_wait.parity.acquire.cta.shared::cta.b64 P, [%0], %1, 0x989680;\n\t"
        "@P bra.uni WD_%=;\n\t"
        "bra.uni WL_%=;\n\t"
        "WD_%=:\n\t}"
        :: "r"(mbar), "r"(parity) : "memory");
}

// ---------------------------------------------------------------------------
// Phase A: E' = emb @ W_ih^T + b_ih.  fp32 GEMM with packed fma.rn.f32x2:
// 128x128 tile, 8x8 microtile held as 8x4 f32x2 pairs.
// ---------------------------------------------------------------------------
__global__ void __launch_bounds__(256) eprime_kernel(
    const float* __restrict__ emb, const float* __restrict__ W_ih,
    const float* __restrict__ b_ih)
{
    __shared__ float As[32][132];
    __shared__ float Bs[32][132];

    const int m0 = blockIdx.x * 128;
    const int n0 = blockIdx.y * 128;
    const int tid = threadIdx.x;
    const int tx = tid & 15;
    const int ty = tid >> 4;

    ull acc2[8][4];
#pragma unroll
    for (int i = 0; i < 8; i++)
#pragma unroll
        for (int j = 0; j < 4; j++) acc2[i][j] = 0ull;

    const int lr = tid >> 3;
    const int lk = (tid & 7) * 4;

    for (int kc = 0; kc < EMBN; kc += 32) {
        __syncthreads();
#pragma unroll
        for (int i = 0; i < 4; i++) {
            int row = lr + i * 32;
            int gm = m0 + row; if (gm > VOCABN - 1) gm = VOCABN - 1;
            float4 va = *(const float4*)&emb[(size_t)gm * EMBN + kc + lk];
            As[lk + 0][row] = va.x; As[lk + 1][row] = va.y;
            As[lk + 2][row] = va.z; As[lk + 3][row] = va.w;
            int gn = n0 + row;
            float4 vb = *(const float4*)&W_ih[(size_t)gn * EMBN + kc + lk];
            Bs[lk + 0][row] = vb.x; Bs[lk + 1][row] = vb.y;
            Bs[lk + 2][row] = vb.z; Bs[lk + 3][row] = vb.w;
        }
        __syncthreads();
#pragma unroll
        for (int k = 0; k < 32; k++) {
            float a[8], bb[8];
            *(float4*)&a[0]  = *(const float4*)&As[k][ty * 8];
            *(float4*)&a[4]  = *(const float4*)&As[k][ty * 8 + 4];
            *(float4*)&bb[0] = *(const float4*)&Bs[k][tx * 8];
            *(float4*)&bb[4] = *(const float4*)&Bs[k][tx * 8 + 4];
            ull b2[4];
#pragma unroll
            for (int j = 0; j < 4; j++) b2[j] = pk2(bb[2 * j], bb[2 * j + 1]);
#pragma unroll
            for (int i = 0; i < 8; i++) {
                ull ad = dup2(a[i]);
#pragma unroll
                for (int j = 0; j < 4; j++)
                    acc2[i][j] = f32x2fma(ad, b2[j], acc2[i][j]);
            }
        }
    }

    float bia[8];
#pragma unroll
    for (int j = 0; j < 8; j++) bia[j] = b_ih[n0 + tx * 8 + j];
#pragma unroll
    for (int i = 0; i < 8; i++) {
        int r = m0 + ty * 8 + i;
        if (r < VOCABN) {
            float c[8];
#pragma unroll
            for (int j = 0; j < 4; j++) upk2(acc2[i][j], c[2 * j], c[2 * j + 1]);
            float4 v0, v1;
            v0.x = c[0] + bia[0]; v0.y = c[1] + bia[1];
            v0.z = c[2] + bia[2]; v0.w = c[3] + bia[3];
            v1.x = c[4] + bia[4]; v1.y = c[5] + bia[5];
            v1.z = c[6] + bia[6]; v1.w = c[7] + bia[7];
            *(float4*)&g_Ep[(size_t)r * G3 + n0 + tx * 8]     = v0;
            *(float4*)&g_Ep[(size_t)r * G3 + n0 + tx * 8 + 4] = v1;
        }
    }
}

// ---------------------------------------------------------------------------
// Phase B: scan. Cluster of 2 CTAs per batch element, 512 threads/CTA.
// Thread = (unit jj = tid>>2, q4 = tid&3): 3 gate dots over 64 cols =
// 32 LOCAL-half cols [rank*128 + q4*32 ..) + 32 PEER-half cols.
// Weights: r(32u), z(32u), n-local(16u) in regs; n-peer(16u) in smem.
// Split-wait: mbarL (128 local-writer arrivals) gates segment A (local cols);
// mbarP (128 peer remote arrivals) gates segment B — segment A executes under
// the peer's DSMEM store/arrive fabric latency.
// Anti-dependence: every arrival is post-shfl_xor_sync of its warp (orders
// all 32 lanes' reads); all 16 warps contain writers, so waitL+waitP passing
// implies all cluster reads of the previous step finished.
// ---------------------------------------------------------------------------
// smem layout (bytes):
//   [0,     40960)  Wn2    512 threads x 16 uints @ 80 B stride (20 uints)
//   [40960, 42240)  h_bf   2 buffers x 8 blocks x 80 B (32 bf16 + 16 pad)
//   [42240, 50432)  tok_s  2048 int32
//   [50432, 50440)  mbarL
//   [50440, 50448)  mbarP
#define SCAN_SMEM 50448
#define HBUF_STRIDE 640   // bytes per h buffer (8 blocks x 80)

__global__ void __cluster_dims__(2, 1, 1) __launch_bounds__(512, 1) scan_kernel(
    const int* __restrict__ tokens, const float* __restrict__ W_hh,
    const float* __restrict__ b_hh, const float* __restrict__ W_fc,
    const float* __restrict__ b_fc, float* __restrict__ out)
{
    extern __shared__ char smem[];
    unsigned* Wn2   = (unsigned*)smem;
    char*     h_raw = smem + 40960;
    int*      tok_s = (int*)(smem + 42240);
    const unsigned mbarL = smem_u32(smem + 50432);
    const unsigned mbarP = smem_u32(smem + 50440);

    const int tid = threadIdx.x;
    const int b   = blockIdx.x >> 1;
    unsigned rank;
    asm("mov.u32 %0, %%cluster_ctarank;" : "=r"(rank));
    const unsigned peer = rank ^ 1u;
    const int jj = tid >> 2;              // local hidden unit 0..127
    const int q4 = tid & 3;               // column quarter-of-half
    const int gj = (int)rank * 128 + jj;  // global hidden unit

    // ---- init: weights ----
    // local cols: rank*128 + q4*32 ..+32 ; peer cols: peer*128 + q4*32 ..+32
    unsigned wr_r[32], wr_z[32], wr_n[16];
    {
        const float2* pr = (const float2*)(W_hh + (size_t)(gj)       * HIDN);
        const float2* pz = (const float2*)(W_hh + (size_t)(256 + gj) * HIDN);
        const float2* pn = (const float2*)(W_hh + (size_t)(512 + gj) * HIDN);
        const int clh = (int)rank * 64 + q4 * 16;   // float2 index, local half
        const int cph = (int)peer * 64 + q4 * 16;   // float2 index, peer half
        unsigned* wd = Wn2 + tid * 20;
#pragma unroll
        for (int i = 0; i < 16; i++) {
            float2 f;
            f = pr[clh + i]; wr_r[i]      = pack_bf2(f.x, f.y);
            f = pr[cph + i]; wr_r[16 + i] = pack_bf2(f.x, f.y);
            f = pz[clh + i]; wr_z[i]      = pack_bf2(f.x, f.y);
            f = pz[cph + i]; wr_z[16 + i] = pack_bf2(f.x, f.y);
            f = pn[clh + i]; wr_n[i]      = pack_bf2(f.x, f.y);
            f = pn[cph + i]; wd[i]        = pack_bf2(f.x, f.y);
        }
    }
    const float bhr = b_hh[gj];
    const float bhz = b_hh[256 + gj];
    const float bhn = b_hh[512 + gj];

    for (int i = tid; i < SEQT; i += 512) tok_s[i] = tokens[b * SEQT + i];
    for (int i = tid; i < 2 * HBUF_STRIDE / 4; i += 512) ((unsigned*)h_raw)[i] = 0u;
    if (tid == 0) {
        asm volatile("mbarrier.init.shared.b64 [%0], %1;" :: "r"(mbarL), "r"(128u) : "memory");
        asm volatile("mbarrier.init.shared.b64 [%0], %1;" :: "r"(mbarP), "r"(128u) : "memory");
    }
    __syncthreads();
    asm volatile("barrier.cluster.arrive.aligned;" ::: "memory");
    asm volatile("barrier.cluster.wait.aligned;"  ::: "memory");

    // prime phase 0 of both mbars (h(0) is ready; cluster sync done above)
    if (q4 == 0) {
        asm volatile("mbarrier.arrive.release.cta.shared::cta.b64 _, [%0];"
                     :: "r"(mbarL) : "memory");
        asm volatile(
            "{ .reg .u32 ra; mapa.shared::cluster.u32 ra, %0, %1;"
            "  mbarrier.arrive.release.cluster.shared::cluster.b64 _, [ra]; }"
            :: "r"(mbarP), "r"(peer) : "memory");
    }

    const uint4* wn4 = (const uint4*)(Wn2 + tid * 20);
    const int blkA = (int)rank * 4 + q4;          // local-half h block
    const int blkB = (int)peer * 4 + q4;          // peer-half h block
    const int hoff = (gj >> 5) * 80 + (gj & 31) * 2;  // this unit's h slot
    const float bhn4 = 0.25f * bhn;
    float hreg = 0.f;

    // gi preactivations for t=0 (r,z biases folded in)
    const float* ep0 = &g_Ep[(size_t)tok_s[0] * G3];
    float gir = __ldg(ep0 + gj)       + bhr;
    float giz = __ldg(ep0 + 256 + gj) + bhz;
    float gin = __ldg(ep0 + 512 + gj);

    for (int t = 0; t < SEQT; t++) {
        const int cur = t & 1;
        const int nxt = cur ^ 1;
        const unsigned par = (unsigned)(t & 1);

        // prefetch next step's preactivations (independent of h)
        const int tn = (t + 1 < SEQT) ? tok_s[t + 1] : tok_s[t];
        const float* epn = &g_Ep[(size_t)tn * G3];
        float girn = __ldg(epn + gj);
        float gizn = __ldg(epn + 256 + gj);
        float ginn = __ldg(epn + 512 + gj);

        unsigned ar0 = 0u, ar1 = 0u, az0 = 0u, az1 = 0u, an0 = 0u, an1 = 0u;

        // ---- segment A: local-half 32 cols (all-register weights) ----
        mbar_wait(mbarL, par);
        {
            const uint4* hA = (const uint4*)(h_raw + cur * HBUF_STRIDE + blkA * 80);
#pragma unroll
            for (int k = 0; k < 4; k++) {
                uint4 h = hA[k];
                ar0 = bffma2(wr_r[4 * k + 0], h.x, ar0);
                ar1 = bffma2(wr_r[4 * k + 1], h.y, ar1);
                az0 = bffma2(wr_z[4 * k + 0], h.x, az0);
                az1 = bffma2(wr_z[4 * k + 1], h.y, az1);
                an0 = bffma2(wr_n[4 * k + 0], h.x, an0);
                an1 = bffma2(wr_n[4 * k + 1], h.y, an1);
                ar0 = bffma2(wr_r[4 * k + 2], h.z, ar0);
                ar1 = bffma2(wr_r[4 * k + 3], h.w, ar1);
                az0 = bffma2(wr_z[4 * k + 2], h.z, az0);
                az1 = bffma2(wr_z[4 * k + 3], h.w, az1);
                an0 = bffma2(wr_n[4 * k + 2], h.z, an0);
                an1 = bffma2(wr_n[4 * k + 3], h.w, an1);
            }
        }

        // ---- segment B: peer-half 32 cols (n weights from smem) ----
        mbar_wait(mbarP, par);
        {
            const uint4* hB = (const uint4*)(h_raw + cur * HBUF_STRIDE + blkB * 80);
#pragma unroll
            for (int k = 0; k < 4; k++) {
                uint4 h = hB[k];
                uint4 w = wn4[k];
                ar0 = bffma2(wr_r[16 + 4 * k + 0], h.x, ar0);
                ar1 = bffma2(wr_r[16 + 4 * k + 1], h.y, ar1);
                az0 = bffma2(wr_z[16 + 4 * k + 0], h.x, az0);
                az1 = bffma2(wr_z[16 + 4 * k + 1], h.y, az1);
                an0 = bffma2(w.x, h.x, an0);
                an1 = bffma2(w.y, h.y, an1);
                ar0 = bffma2(wr_r[16 + 4 * k + 2], h.z, ar0);
                ar1 = bffma2(wr_r[16 + 4 * k + 3], h.w, ar1);
                az0 = bffma2(wr_z[16 + 4 * k + 2], h.z, az0);
                az1 = bffma2(wr_z[16 + 4 * k + 3], h.w, az1);
                an0 = bffma2(w.z, h.z, an0);
                an1 = bffma2(w.w, h.w, an1);
            }
        }

        float sr = (bflo(ar0) + bfhi(ar0)) + (bflo(ar1) + bfhi(ar1));
        float sz = (bflo(az0) + bfhi(az0)) + (bflo(az1) + bfhi(az1));
        float sn = (bflo(an0) + bfhi(an0)) + (bflo(an1) + bfhi(an1)) + bhn4;

        // 4-way reduce across the quarter group (lanes xor 1, xor 2)
        sr += __shfl_xor_sync(0xffffffffu, sr, 1);
        sz += __shfl_xor_sync(0xffffffffu, sz, 1);
        sn += __shfl_xor_sync(0xffffffffu, sn, 1);
        sr += __shfl_xor_sync(0xffffffffu, sr, 2);
        sz += __shfl_xor_sync(0xffffffffu, sz, 2);
        sn += __shfl_xor_sync(0xffffffffu, sn, 2);

        // ---- epilogue (all 4 threads redundantly; q4==0 stores) ----
        float r  = sigapx(gir + sr);
        float z  = sigapx(giz + sz);
        float n  = tanhapx(fmaf(r, sn, gin));    // sn already holds bhn
        float hn = fmaf(z, hreg - n, n);         // (1-z)*n + z*h
        hreg = hn;

        if (q4 == 0) {
            __nv_bfloat16 hb = __float2bfloat16(hn);
            unsigned short hb16 = *(unsigned short*)&hb;
            char* dstp = h_raw + nxt * HBUF_STRIDE + hoff;
            unsigned dst = smem_u32(dstp);
            // remote first: start the fabric latency as early as possible
            asm volatile(
                "{ .reg .u32 ra; mapa.shared::cluster.u32 ra, %0, %1;"
                "  st.shared::cluster.u16 [ra], %2; }"
                :: "r"(dst), "r"(peer), "h"(hb16) : "memory");
            asm volatile(
                "{ .reg .u32 ra; mapa.shared::cluster.u32 ra, %0, %1;"
                "  mbarrier.arrive.release.cluster.shared::cluster.b64 _, [ra]; }"
                :: "r"(mbarP), "r"(peer) : "memory");
            *(__nv_bfloat16*)dstp = hb;          // local store
            asm volatile("mbarrier.arrive.release.cta.shared::cta.b64 _, [%0];"
                         :: "r"(mbarL) : "memory");
        }
        gir = girn + bhr;
        giz = gizn + bhz;
        gin = ginn;
    }

    // sync final stores (phase of step SEQT has parity SEQT&1 = 0)
    mbar_wait(mbarL, 0u);
    mbar_wait(mbarP, 0u);

    // ---- final FC + sigmoid: final h lives in buffer 0 (2048 even) ----
    if (rank == 0 && tid < 64) {
        const int o = tid >> 5;
        const int lane = tid & 31;
        float s = 0.f;
#pragma unroll
        for (int i = 0; i < 8; i++) {
            int k = lane * 8 + i;
            const __nv_bfloat16* hp =
                (const __nv_bfloat16*)(h_raw + (k >> 5) * 80 + (k & 31) * 2);
            s = fmaf(__bfloat162float(*hp), W_fc[o * HIDN + k], s);
        }
#pragma unroll
        for (int off = 16; off; off >>= 1)
            s += __shfl_xor_sync(0xffffffffu, s, off);
        if (lane == 0) out[b * 2 + o] = __fdividef(1.f, 1.f + __expf(-(s + b_fc[o])));
    }
}

// ---------------------------------------------------------------------------
// launch
// ---------------------------------------------------------------------------
extern "C" void kernel_launch(void* const* d_in, const int* in_sizes, int n_in,
                              void* d_out, int out_size)
{
    const int*   tokens = (const int*)  d_in[0];
    const float* emb    = (const float*)d_in[1];
    const float* W_ih   = (const float*)d_in[2];
    const float* W_hh   = (const float*)d_in[3];
    const float* b_ih   = (const float*)d_in[4];
    const float* b_hh   = (const float*)d_in[5];
    const float* W_fc   = (const float*)d_in[6];
    const float* b_fc   = (const float*)d_in[7];
    float* out = (float*)d_out;

    cudaFuncSetAttribute(scan_kernel,
                         cudaFuncAttributeMaxDynamicSharedMemorySize, SCAN_SMEM);

    dim3 gA((VOCABN + 127) / 128, G3 / 128);
    eprime_kernel<<<gA, 256>>>(emb, W_ih, b_ih);

    scan_kernel<<<2 * NBATCH, 512, SCAN_SMEM>>>(tokens, W_hh, b_hh, W_fc, b_fc, out);

    (void)in_sizes; (void)n_in; (void)out_size;
}

// round 11
// speedup vs baseline: 2.0279x; 1.0903x over previous
#include <cuda_runtime.h>
#include <cuda_bf16.h>
#include <cstdint>
#include <cstddef>

#define VOCABN 50257
#define EMBN   256
#define HIDN   256
#define NBATCH 64
#define SEQT   2048
#define G3     768

// 154 MB scratch: E'[v][j] = emb[v] . W_ih[j] + b_ih[j]
__device__ float g_Ep[(size_t)VOCABN * G3];

typedef unsigned long long ull;

// ---------------------------------------------------------------------------
// helpers
// ---------------------------------------------------------------------------
__device__ __forceinline__ float bflo(unsigned u) { return __uint_as_float(u << 16); }
__device__ __forceinline__ float bfhi(unsigned u) { return __uint_as_float(u & 0xffff0000u); }
__device__ __forceinline__ float tanhapx(float x) {
    float y;
    asm("tanh.approx.f32 %0, %1;" : "=f"(y) : "f"(x));
    return y;
}
__device__ __forceinline__ float sigapx(float x) {   // 0.5 + 0.5*tanh(x/2)
    return fmaf(0.5f, tanhapx(0.5f * x), 0.5f);
}
__device__ __forceinline__ unsigned smem_u32(const void* p) {
    unsigned a;
    asm("{ .reg .u64 t; cvta.to.shared.u64 t, %1; cvt.u32.u64 %0, t; }" : "=r"(a) : "l"(p));
    return a;
}
__device__ __forceinline__ unsigned bffma2(unsigned a, unsigned b, unsigned c) {
    unsigned d;
    asm("fma.rn.bf16x2 %0, %1, %2, %3;" : "=r"(d) : "r"(a), "r"(b), "r"(c));
    return d;
}
__device__ __forceinline__ unsigned pack_bf2(float lo, float hi) {
    __nv_bfloat162 p = __floats2bfloat162_rn(lo, hi);
    return *(unsigned*)&p;
}
__device__ __forceinline__ void mbar_wait(unsigned mbar, unsigned parity) {
    asm volatile(
        "{\n\t.reg .pred P;\n\t"
        "WL_%=:\n\t"
        "mbarrier.try_wait.parity.acquire.cta.shared::cta.b64 P, [%0], %1, 0x989680;\n\t"
        "@P bra.uni WD_%=;\n\t"
        "bra.uni WL_%=;\n\t"
        "WD_%=:\n\t}"
        :: "r"(mbar), "r"(parity) : "memory");
}
__device__ __forceinline__ void mma16816(float* c,
    unsigned a0, unsigned a1, unsigned a2, unsigned a3,
    unsigned b0, unsigned b1)
{
    asm("mma.sync.aligned.m16n8k16.row.col.f32.bf16.bf16.f32 "
        "{%0,%1,%2,%3}, {%4,%5,%6,%7}, {%8,%9}, {%0,%1,%2,%3};"
        : "+f"(c[0]), "+f"(c[1]), "+f"(c[2]), "+f"(c[3])
        : "r"(a0), "r"(a1), "r"(a2), "r"(a3), "r"(b0), "r"(b1));
}

// ---------------------------------------------------------------------------
// Phase A: E' = emb @ W_ih^T + b_ih via bf16 mma.sync (tensor pipe).
// Block: 256 thr (8 warps), M tile = 128 rows (warp = m16 slab), N chunks
// of 64 staged in smem, K = 256 (16 k16 steps). fp32 accumulate + bias.
// smem rows padded to 132 words so fragment LDS (addr 4g+t mod 32) is
// bank-conflict-free.
// ---------------------------------------------------------------------------
#define AW 132                       // words per smem row (256 bf16 = 128 + 4 pad)
#define EPR_SMEM ((128 + 64) * AW * 4)   // 101376 B

__global__ void __launch_bounds__(256) eprime_tc_kernel(
    const float* __restrict__ emb, const float* __restrict__ W_ih,
    const float* __restrict__ b_ih)
{
    extern __shared__ unsigned ts[];
    unsigned* sA = ts;                 // 128 x 132 words
    unsigned* sB = ts + 128 * AW;      // 64 x 132 words

    const int tid  = threadIdx.x;
    const int m0   = blockIdx.x * 128;
    const int warp = tid >> 5;
    const int lane = tid & 31;
    const int g    = lane >> 2;        // 0..7
    const int t    = lane & 3;         // 0..3
    const int mrow = warp * 16;

    // fill A tile (f32 -> bf16 pairs), 128 rows x 128 words
    for (int i = tid; i < 128 * 128; i += 256) {
        int r = i >> 7, w = i & 127;
        int gm = m0 + r; if (gm >= VOCABN) gm = VOCABN - 1;
        float2 f = *(const float2*)&emb[(size_t)gm * EMBN + w * 2];
        sA[r * AW + w] = pack_bf2(f.x, f.y);
    }

    for (int nb = 0; nb < 12; nb++) {
        __syncthreads();               // previous chunk's reads done (also fences A fill)
        for (int i = tid; i < 64 * 128; i += 256) {
            int r = i >> 7, w = i & 127;
            float2 f = *(const float2*)&W_ih[(size_t)(nb * 64 + r) * EMBN + w * 2];
            sB[r * AW + w] = pack_bf2(f.x, f.y);
        }
        __syncthreads();

        float acc[8][4];
#pragma unroll
        for (int nf = 0; nf < 8; nf++)
#pragma unroll
            for (int j = 0; j < 4; j++) acc[nf][j] = 0.f;

#pragma unroll 4
        for (int ks = 0; ks < 16; ks++) {
            const int kw = ks * 8;
            unsigned a0 = sA[(mrow + g)     * AW + kw + t];
            unsigned a1 = sA[(mrow + g + 8) * AW + kw + t];
            unsigned a2 = sA[(mrow + g)     * AW + kw + 4 + t];
            unsigned a3 = sA[(mrow + g + 8) * AW + kw + 4 + t];
#pragma unroll
            for (int nf = 0; nf < 8; nf++) {
                unsigned b0 = sB[(nf * 8 + g) * AW + kw + t];
                unsigned b1 = sB[(nf * 8 + g) * AW + kw + 4 + t];
                mma16816(acc[nf], a0, a1, a2, a3, b0, b1);
            }
        }

        // store with bias: c0,c1 -> (row g, n 2t/2t+1); c2,c3 -> (row g+8)
#pragma unroll
        for (int nf = 0; nf < 8; nf++) {
            int n  = nb * 64 + nf * 8 + 2 * t;
            float bi0 = b_ih[n], bi1 = b_ih[n + 1];
            int r0 = m0 + mrow + g;
            int r1 = r0 + 8;
            if (r0 < VOCABN) {
                float2 v; v.x = acc[nf][0] + bi0; v.y = acc[nf][1] + bi1;
                *(float2*)&g_Ep[(size_t)r0 * G3 + n] = v;
            }
            if (r1 < VOCABN) {
                float2 v; v.x = acc[nf][2] + bi0; v.y = acc[nf][3] + bi1;
                *(float2*)&g_Ep[(size_t)r1 * G3 + n] = v;
            }
        }
    }
}

// ---------------------------------------------------------------------------
// Phase B: scan. Cluster of 2 CTAs per batch element, 512 threads/CTA.
// (unchanged from R9 — proven at 2.247 ms)
// Thread = (unit jj = tid>>2, q4 = tid&3): 3 gate dots over 64 cols =
// 32 LOCAL-half cols + 32 PEER-half cols. Weights: r(32u), z(32u),
// n-local(16u) in regs; n-peer(16u) in smem. Split-wait: mbarL gates the
// local segment; mbarP gates the peer segment (local work hides fabric).
// ---------------------------------------------------------------------------
// smem layout (bytes):
//   [0,     40960)  Wn2    512 threads x 16 uints @ 80 B stride (20 uints)
//   [40960, 42240)  h_bf   2 buffers x 8 blocks x 80 B (32 bf16 + 16 pad)
//   [42240, 50432)  tok_s  2048 int32
//   [50432, 50440)  mbarL
//   [50440, 50448)  mbarP
#define SCAN_SMEM 50448
#define HBUF_STRIDE 640   // bytes per h buffer (8 blocks x 80)

__global__ void __cluster_dims__(2, 1, 1) __launch_bounds__(512, 1) scan_kernel(
    const int* __restrict__ tokens, const float* __restrict__ W_hh,
    const float* __restrict__ b_hh, const float* __restrict__ W_fc,
    const float* __restrict__ b_fc, float* __restrict__ out)
{
    extern __shared__ char smem[];
    unsigned* Wn2   = (unsigned*)smem;
    char*     h_raw = smem + 40960;
    int*      tok_s = (int*)(smem + 42240);
    const unsigned mbarL = smem_u32(smem + 50432);
    const unsigned mbarP = smem_u32(smem + 50440);

    const int tid = threadIdx.x;
    const int b   = blockIdx.x >> 1;
    unsigned rank;
    asm("mov.u32 %0, %%cluster_ctarank;" : "=r"(rank));
    const unsigned peer = rank ^ 1u;
    const int jj = tid >> 2;
    const int q4 = tid & 3;
    const int gj = (int)rank * 128 + jj;

    unsigned wr_r[32], wr_z[32], wr_n[16];
    {
        const float2* pr = (const float2*)(W_hh + (size_t)(gj)       * HIDN);
        const float2* pz = (const float2*)(W_hh + (size_t)(256 + gj) * HIDN);
        const float2* pn = (const float2*)(W_hh + (size_t)(512 + gj) * HIDN);
        const int clh = (int)rank * 64 + q4 * 16;
        const int cph = (int)peer * 64 + q4 * 16;
        unsigned* wd = Wn2 + tid * 20;
#pragma unroll
        for (int i = 0; i < 16; i++) {
            float2 f;
            f = pr[clh + i]; wr_r[i]      = pack_bf2(f.x, f.y);
            f = pr[cph + i]; wr_r[16 + i] = pack_bf2(f.x, f.y);
            f = pz[clh + i]; wr_z[i]      = pack_bf2(f.x, f.y);
            f = pz[cph + i]; wr_z[16 + i] = pack_bf2(f.x, f.y);
            f = pn[clh + i]; wr_n[i]      = pack_bf2(f.x, f.y);
            f = pn[cph + i]; wd[i]        = pack_bf2(f.x, f.y);
        }
    }
    const float bhr = b_hh[gj];
    const float bhz = b_hh[256 + gj];
    const float bhn = b_hh[512 + gj];

    for (int i = tid; i < SEQT; i += 512) tok_s[i] = tokens[b * SEQT + i];
    for (int i = tid; i < 2 * HBUF_STRIDE / 4; i += 512) ((unsigned*)h_raw)[i] = 0u;
    if (tid == 0) {
        asm volatile("mbarrier.init.shared.b64 [%0], %1;" :: "r"(mbarL), "r"(128u) : "memory");
        asm volatile("mbarrier.init.shared.b64 [%0], %1;" :: "r"(mbarP), "r"(128u) : "memory");
    }
    __syncthreads();
    asm volatile("barrier.cluster.arrive.aligned;" ::: "memory");
    asm volatile("barrier.cluster.wait.aligned;"  ::: "memory");

    if (q4 == 0) {
        asm volatile("mbarrier.arrive.release.cta.shared::cta.b64 _, [%0];"
                     :: "r"(mbarL) : "memory");
        asm volatile(
            "{ .reg .u32 ra; mapa.shared::cluster.u32 ra, %0, %1;"
            "  mbarrier.arrive.release.cluster.shared::cluster.b64 _, [ra]; }"
            :: "r"(mbarP), "r"(peer) : "memory");
    }

    const uint4* wn4 = (const uint4*)(Wn2 + tid * 20);
    const int blkA = (int)rank * 4 + q4;
    const int blkB = (int)peer * 4 + q4;
    const int hoff = (gj >> 5) * 80 + (gj & 31) * 2;
    const float bhn4 = 0.25f * bhn;
    float hreg = 0.f;

    const float* ep0 = &g_Ep[(size_t)tok_s[0] * G3];
    float gir = __ldg(ep0 + gj)       + bhr;
    float giz = __ldg(ep0 + 256 + gj) + bhz;
    float gin = __ldg(ep0 + 512 + gj);

    for (int t = 0; t < SEQT; t++) {
        const int cur = t & 1;
        const int nxt = cur ^ 1;
        const unsigned par = (unsigned)(t & 1);

        const int tn = (t + 1 < SEQT) ? tok_s[t + 1] : tok_s[t];
        const float* epn = &g_Ep[(size_t)tn * G3];
        float girn = __ldg(epn + gj);
        float gizn = __ldg(epn + 256 + gj);
        float ginn = __ldg(epn + 512 + gj);

        unsigned ar0 = 0u, ar1 = 0u, az0 = 0u, az1 = 0u, an0 = 0u, an1 = 0u;

        mbar_wait(mbarL, par);
        {
            const uint4* hA = (const uint4*)(h_raw + cur * HBUF_STRIDE + blkA * 80);
#pragma unroll
            for (int k = 0; k < 4; k++) {
                uint4 h = hA[k];
                ar0 = bffma2(wr_r[4 * k + 0], h.x, ar0);
                ar1 = bffma2(wr_r[4 * k + 1], h.y, ar1);
                az0 = bffma2(wr_z[4 * k + 0], h.x, az0);
                az1 = bffma2(wr_z[4 * k + 1], h.y, az1);
                an0 = bffma2(wr_n[4 * k + 0], h.x, an0);
                an1 = bffma2(wr_n[4 * k + 1], h.y, an1);
                ar0 = bffma2(wr_r[4 * k + 2], h.z, ar0);
                ar1 = bffma2(wr_r[4 * k + 3], h.w, ar1);
                az0 = bffma2(wr_z[4 * k + 2], h.z, az0);
                az1 = bffma2(wr_z[4 * k + 3], h.w, az1);
                an0 = bffma2(wr_n[4 * k + 2], h.z, an0);
                an1 = bffma2(wr_n[4 * k + 3], h.w, an1);
            }
        }

        mbar_wait(mbarP, par);
        {
            const uint4* hB = (const uint4*)(h_raw + cur * HBUF_STRIDE + blkB * 80);
#pragma unroll
            for (int k = 0; k < 4; k++) {
                uint4 h = hB[k];
                uint4 w = wn4[k];
                ar0 = bffma2(wr_r[16 + 4 * k + 0], h.x, ar0);
                ar1 = bffma2(wr_r[16 + 4 * k + 1], h.y, ar1);
                az0 = bffma2(wr_z[16 + 4 * k + 0], h.x, az0);
                az1 = bffma2(wr_z[16 + 4 * k + 1], h.y, az1);
                an0 = bffma2(w.x, h.x, an0);
                an1 = bffma2(w.y, h.y, an1);
                ar0 = bffma2(wr_r[16 + 4 * k + 2], h.z, ar0);
                ar1 = bffma2(wr_r[16 + 4 * k + 3], h.w, ar1);
                az0 = bffma2(wr_z[16 + 4 * k + 2], h.z, az0);
                az1 = bffma2(wr_z[16 + 4 * k + 3], h.w, az1);
                an0 = bffma2(w.z, h.z, an0);
                an1 = bffma2(w.w, h.w, an1);
            }
        }

        float sr = (bflo(ar0) + bfhi(ar0)) + (bflo(ar1) + bfhi(ar1));
        float sz = (bflo(az0) + bfhi(az0)) + (bflo(az1) + bfhi(az1));
        float sn = (bflo(an0) + bfhi(an0)) + (bflo(an1) + bfhi(an1)) + bhn4;

        sr += __shfl_xor_sync(0xffffffffu, sr, 1);
        sz += __shfl_xor_sync(0xffffffffu, sz, 1);
        sn += __shfl_xor_sync(0xffffffffu, sn, 1);
        sr += __shfl_xor_sync(0xffffffffu, sr, 2);
        sz += __shfl_xor_sync(0xffffffffu, sz, 2);
        sn += __shfl_xor_sync(0xffffffffu, sn, 2);

        float r  = sigapx(gir + sr);
        float z  = sigapx(giz + sz);
        float n  = tanhapx(fmaf(r, sn, gin));
        float hn = fmaf(z, hreg - n, n);
        hreg = hn;

        if (q4 == 0) {
            __nv_bfloat16 hb = __float2bfloat16(hn);
            unsigned short hb16 = *(unsigned short*)&hb;
            char* dstp = h_raw + nxt * HBUF_STRIDE + hoff;
            unsigned dst = smem_u32(dstp);
            asm volatile(
                "{ .reg .u32 ra; mapa.shared::cluster.u32 ra, %0, %1;"
                "  st.shared::cluster.u16 [ra], %2; }"
                :: "r"(dst), "r"(peer), "h"(hb16) : "memory");
            asm volatile(
                "{ .reg .u32 ra; mapa.shared::cluster.u32 ra, %0, %1;"
                "  mbarrier.arrive.release.cluster.shared::cluster.b64 _, [ra]; }"
                :: "r"(mbarP), "r"(peer) : "memory");
            *(__nv_bfloat16*)dstp = hb;
            asm volatile("mbarrier.arrive.release.cta.shared::cta.b64 _, [%0];"
                         :: "r"(mbarL) : "memory");
        }
        gir = girn + bhr;
        giz = gizn + bhz;
        gin = ginn;
    }

    mbar_wait(mbarL, 0u);
    mbar_wait(mbarP, 0u);

    if (rank == 0 && tid < 64) {
        const int o = tid >> 5;
        const int lane = tid & 31;
        float s = 0.f;
#pragma unroll
        for (int i = 0; i < 8; i++) {
            int k = lane * 8 + i;
            const __nv_bfloat16* hp =
                (const __nv_bfloat16*)(h_raw + (k >> 5) * 80 + (k & 31) * 2);
            s = fmaf(__bfloat162float(*hp), W_fc[o * HIDN + k], s);
        }
#pragma unroll
        for (int off = 16; off; off >>= 1)
            s += __shfl_xor_sync(0xffffffffu, s, off);
        if (lane == 0) out[b * 2 + o] = __fdividef(1.f, 1.f + __expf(-(s + b_fc[o])));
    }
}

// ---------------------------------------------------------------------------
// launch
// ---------------------------------------------------------------------------
extern "C" void kernel_launch(void* const* d_in, const int* in_sizes, int n_in,
                              void* d_out, int out_size)
{
    const int*   tokens = (const int*)  d_in[0];
    const float* emb    = (const float*)d_in[1];
    const float* W_ih   = (const float*)d_in[2];
    const float* W_hh   = (const float*)d_in[3];
    const float* b_ih   = (const float*)d_in[4];
    const float* b_hh   = (const float*)d_in[5];
    const float* W_fc   = (const float*)d_in[6];
    const float* b_fc   = (const float*)d_in[7];
    float* out = (float*)d_out;

    cudaFuncSetAttribute(eprime_tc_kernel,
                         cudaFuncAttributeMaxDynamicSharedMemorySize, EPR_SMEM);
    cudaFuncSetAttribute(scan_kernel,
                         cudaFuncAttributeMaxDynamicSharedMemorySize, SCAN_SMEM);

    eprime_tc_kernel<<<(VOCABN + 127) / 128, 256, EPR_SMEM>>>(emb, W_ih, b_ih);

    scan_kernel<<<2 * NBATCH, 512, SCAN_SMEM>>>(tokens, W_hh, b_hh, W_fc, b_fc, out);

    (void)in_sizes; (void)n_in; (void)out_size;
}

// round 12
// speedup vs baseline: 2.1571x; 1.0637x over previous
#include <cuda_runtime.h>
#include <cuda_bf16.h>
#include <cstdint>
#include <cstddef>

#define VOCABN 50257
#define EMBN   256
#define HIDN   256
#define NBATCH 64
#define SEQT   2048
#define G3     768

// 154 MB scratch: E'[v][j] = emb[v] . W_ih[j] + b_ih[j]
__device__ float g_Ep[(size_t)VOCABN * G3];

// ---------------------------------------------------------------------------
// helpers
// ---------------------------------------------------------------------------
__device__ __forceinline__ float bflo(unsigned u) { return __uint_as_float(u << 16); }
__device__ __forceinline__ float bfhi(unsigned u) { return __uint_as_float(u & 0xffff0000u); }
__device__ __forceinline__ float tanhapx(float x) {
    float y;
    asm("tanh.approx.f32 %0, %1;" : "=f"(y) : "f"(x));
    return y;
}
__device__ __forceinline__ float sigapx(float x) {   // 0.5 + 0.5*tanh(x/2)
    return fmaf(0.5f, tanhapx(0.5f * x), 0.5f);
}
__device__ __forceinline__ unsigned smem_u32(const void* p) {
    unsigned a;
    asm("{ .reg .u64 t; cvta.to.shared.u64 t, %1; cvt.u32.u64 %0, t; }" : "=r"(a) : "l"(p));
    return a;
}
__device__ __forceinline__ unsigned bffma2(unsigned a, unsigned b, unsigned c) {
    unsigned d;
    asm("fma.rn.bf16x2 %0, %1, %2, %3;" : "=r"(d) : "r"(a), "r"(b), "r"(c));
    return d;
}
__device__ __forceinline__ unsigned pack_bf2(float lo, float hi) {
    __nv_bfloat162 p = __floats2bfloat162_rn(lo, hi);
    return *(unsigned*)&p;
}
__device__ __forceinline__ void mbar_wait(unsigned mbar, unsigned parity) {
    asm volatile(
        "{\n\t.reg .pred P;\n\t"
        "WL_%=:\n\t"
        "mbarrier.try_wait.parity.acquire.cta.shared::cta.b64 P, [%0], %1, 0x989680;\n\t"
        "@P bra.uni WD_%=;\n\t"
        "bra.uni WL_%=;\n\t"
        "WD_%=:\n\t}"
        :: "r"(mbar), "r"(parity) : "memory");
}
__device__ __forceinline__ void mma16816(float* c,
    unsigned a0, unsigned a1, unsigned a2, unsigned a3,
    unsigned b0, unsigned b1)
{
    asm("mma.sync.aligned.m16n8k16.row.col.f32.bf16.bf16.f32 "
        "{%0,%1,%2,%3}, {%4,%5,%6,%7}, {%8,%9}, {%0,%1,%2,%3};"
        : "+f"(c[0]), "+f"(c[1]), "+f"(c[2]), "+f"(c[3])
        : "r"(a0), "r"(a1), "r"(a2), "r"(a3), "r"(b0), "r"(b1));
}

// ---------------------------------------------------------------------------
// Phase A: E' = emb @ W_ih^T + b_ih via bf16 mma.sync (unchanged from R11).
// ---------------------------------------------------------------------------
#define AW 132
#define EPR_SMEM ((128 + 64) * AW * 4)   // 101376 B

__global__ void __launch_bounds__(256) eprime_tc_kernel(
    const float* __restrict__ emb, const float* __restrict__ W_ih,
    const float* __restrict__ b_ih)
{
    extern __shared__ unsigned ts[];
    unsigned* sA = ts;                 // 128 x 132 words
    unsigned* sB = ts + 128 * AW;      // 64 x 132 words

    const int tid  = threadIdx.x;
    const int m0   = blockIdx.x * 128;
    const int warp = tid >> 5;
    const int lane = tid & 31;
    const int g    = lane >> 2;
    const int t    = lane & 3;
    const int mrow = warp * 16;

    for (int i = tid; i < 128 * 128; i += 256) {
        int r = i >> 7, w = i & 127;
        int gm = m0 + r; if (gm >= VOCABN) gm = VOCABN - 1;
        float2 f = *(const float2*)&emb[(size_t)gm * EMBN + w * 2];
        sA[r * AW + w] = pack_bf2(f.x, f.y);
    }

    for (int nb = 0; nb < 12; nb++) {
        __syncthreads();
        for (int i = tid; i < 64 * 128; i += 256) {
            int r = i >> 7, w = i & 127;
            float2 f = *(const float2*)&W_ih[(size_t)(nb * 64 + r) * EMBN + w * 2];
            sB[r * AW + w] = pack_bf2(f.x, f.y);
        }
        __syncthreads();

        float acc[8][4];
#pragma unroll
        for (int nf = 0; nf < 8; nf++)
#pragma unroll
            for (int j = 0; j < 4; j++) acc[nf][j] = 0.f;

#pragma unroll 4
        for (int ks = 0; ks < 16; ks++) {
            const int kw = ks * 8;
            unsigned a0 = sA[(mrow + g)     * AW + kw + t];
            unsigned a1 = sA[(mrow + g + 8) * AW + kw + t];
            unsigned a2 = sA[(mrow + g)     * AW + kw + 4 + t];
            unsigned a3 = sA[(mrow + g + 8) * AW + kw + 4 + t];
#pragma unroll
            for (int nf = 0; nf < 8; nf++) {
                unsigned b0 = sB[(nf * 8 + g) * AW + kw + t];
                unsigned b1 = sB[(nf * 8 + g) * AW + kw + 4 + t];
                mma16816(acc[nf], a0, a1, a2, a3, b0, b1);
            }
        }

#pragma unroll
        for (int nf = 0; nf < 8; nf++) {
            int n  = nb * 64 + nf * 8 + 2 * t;
            float bi0 = b_ih[n], bi1 = b_ih[n + 1];
            int r0 = m0 + mrow + g;
            int r1 = r0 + 8;
            if (r0 < VOCABN) {
                float2 v; v.x = acc[nf][0] + bi0; v.y = acc[nf][1] + bi1;
                *(float2*)&g_Ep[(size_t)r0 * G3 + n] = v;
            }
            if (r1 < VOCABN) {
                float2 v; v.x = acc[nf][2] + bi0; v.y = acc[nf][3] + bi1;
                *(float2*)&g_Ep[(size_t)r1 * G3 + n] = v;
            }
        }
    }
}

// ---------------------------------------------------------------------------
// Phase B: scan. Cluster of 2 CTAs per batch element, 256 FAT threads/CTA.
// Thread = (unit jj = tid>>1, split s = tid&1): 3 gate dots over 128 cols =
// 64 LOCAL cols [rank*128 + s*64 ..) + 64 PEER cols [peer*128 + s*64 ..).
// ALL 192 weight uints live in registers (launch_bounds(256,1) -> 255 regs).
// Split-wait: mbarL gates the local segment, mbarP the peer segment.
// 2-way shfl (xor 1) combines the s pair; epilogue redundant x2; s==0 stores.
// Safety: every arrival is post-shfl_xor_sync of its warp (orders all lanes'
// reads); all 8 warps contain writers, so wait passing implies all previous-
// step reads in the cluster are done.
// ---------------------------------------------------------------------------
// smem layout (bytes):
//   [0,    1152)  h_bf   2 buffers x 4 blocks x 144 B (64 bf16 + 16 pad)
//   [1152, 9344)  tok_s  2048 int32
//   [9344, 9352)  mbarL
//   [9352, 9360)  mbarP
#define SCAN_SMEM 9360
#define HBUF_STRIDE 576   // bytes per h buffer (4 blocks x 144)

__global__ void __cluster_dims__(2, 1, 1) __launch_bounds__(256, 1) scan_kernel(
    const int* __restrict__ tokens, const float* __restrict__ W_hh,
    const float* __restrict__ b_hh, const float* __restrict__ W_fc,
    const float* __restrict__ b_fc, float* __restrict__ out)
{
    extern __shared__ char smem[];
    char* h_raw = smem;
    int*  tok_s = (int*)(smem + 1152);
    const unsigned mbarL = smem_u32(smem + 9344);
    const unsigned mbarP = smem_u32(smem + 9352);

    const int tid = threadIdx.x;
    const int b   = blockIdx.x >> 1;
    unsigned rank;
    asm("mov.u32 %0, %%cluster_ctarank;" : "=r"(rank));
    const unsigned peer = rank ^ 1u;
    const int jj = tid >> 1;              // local hidden unit 0..127
    const int s  = tid & 1;               // column split within each half
    const int gj = (int)rank * 128 + jj;  // global hidden unit

    // ---- init: ALL weights in registers (6 x 32 uints) ----
    unsigned aR[32], aZ[32], aN[32];      // local segment
    unsigned bR[32], bZ[32], bN[32];      // peer segment
    {
        const float2* pr = (const float2*)(W_hh + (size_t)(gj)       * HIDN);
        const float2* pz = (const float2*)(W_hh + (size_t)(256 + gj) * HIDN);
        const float2* pn = (const float2*)(W_hh + (size_t)(512 + gj) * HIDN);
        const int la = (int)rank * 64 + s * 32;   // local float2 base
        const int pa = (int)peer * 64 + s * 32;   // peer float2 base
#pragma unroll
        for (int i = 0; i < 32; i++) {
            float2 f;
            f = pr[la + i]; aR[i] = pack_bf2(f.x, f.y);
            f = pr[pa + i]; bR[i] = pack_bf2(f.x, f.y);
            f = pz[la + i]; aZ[i] = pack_bf2(f.x, f.y);
            f = pz[pa + i]; bZ[i] = pack_bf2(f.x, f.y);
            f = pn[la + i]; aN[i] = pack_bf2(f.x, f.y);
            f = pn[pa + i]; bN[i] = pack_bf2(f.x, f.y);
        }
    }
    const float bhr = b_hh[gj];
    const float bhz = b_hh[256 + gj];
    const float bhn2 = 0.5f * b_hh[512 + gj];

    for (int i = tid; i < SEQT; i += 256) tok_s[i] = tokens[b * SEQT + i];
    for (int i = tid; i < 2 * HBUF_STRIDE / 4; i += 256) ((unsigned*)h_raw)[i] = 0u;
    if (tid == 0) {
        asm volatile("mbarrier.init.shared.b64 [%0], %1;" :: "r"(mbarL), "r"(128u) : "memory");
        asm volatile("mbarrier.init.shared.b64 [%0], %1;" :: "r"(mbarP), "r"(128u) : "memory");
    }
    __syncthreads();
    asm volatile("barrier.cluster.arrive.aligned;" ::: "memory");
    asm volatile("barrier.cluster.wait.aligned;"  ::: "memory");

    // prime phase 0 (h(0) ready; cluster sync above orders inits)
    if (s == 0) {
        asm volatile("mbarrier.arrive.release.cta.shared::cta.b64 _, [%0];"
                     :: "r"(mbarL) : "memory");
        asm volatile(
            "{ .reg .u32 ra; mapa.shared::cluster.u32 ra, %0, %1;"
            "  mbarrier.arrive.release.cluster.shared::cluster.b64 _, [ra]; }"
            :: "r"(mbarP), "r"(peer) : "memory");
    }

    const int blkA = (int)rank * 2 + s;           // local-segment h block
    const int blkB = (int)peer * 2 + s;           // peer-segment h block
    const int hoff = (gj >> 6) * 144 + (gj & 63) * 2;  // writer's h slot
    float hreg = 0.f;

    const float* ep0 = &g_Ep[(size_t)tok_s[0] * G3];
    float gir = __ldg(ep0 + gj)       + bhr;
    float giz = __ldg(ep0 + 256 + gj) + bhz;
    float gin = __ldg(ep0 + 512 + gj);

    for (int t = 0; t < SEQT; t++) {
        const int cur = t & 1;
        const int nxt = cur ^ 1;
        const unsigned par = (unsigned)(t & 1);

        // prefetch next step's preactivations (independent of h)
        const int tn = (t + 1 < SEQT) ? tok_s[t + 1] : tok_s[t];
        const float* epn = &g_Ep[(size_t)tn * G3];
        float girn = __ldg(epn + gj);
        float gizn = __ldg(epn + 256 + gj);
        float ginn = __ldg(epn + 512 + gj);

        unsigned ar0 = 0u, ar1 = 0u, az0 = 0u, az1 = 0u, an0 = 0u, an1 = 0u;

        // ---- segment A: local 64 cols, all-register weights ----
        mbar_wait(mbarL, par);
        {
            const uint4* hA = (const uint4*)(h_raw + cur * HBUF_STRIDE + blkA * 144);
#pragma unroll
            for (int k = 0; k < 8; k++) {
                uint4 h = hA[k];
                ar0 = bffma2(aR[4 * k + 0], h.x, ar0);
                ar1 = bffma2(aR[4 * k + 1], h.y, ar1);
                az0 = bffma2(aZ[4 * k + 0], h.x, az0);
                az1 = bffma2(aZ[4 * k + 1], h.y, az1);
                an0 = bffma2(aN[4 * k + 0], h.x, an0);
                an1 = bffma2(aN[4 * k + 1], h.y, an1);
                ar0 = bffma2(aR[4 * k + 2], h.z, ar0);
                ar1 = bffma2(aR[4 * k + 3], h.w, ar1);
                az0 = bffma2(aZ[4 * k + 2], h.z, az0);
                az1 = bffma2(aZ[4 * k + 3], h.w, az1);
                an0 = bffma2(aN[4 * k + 2], h.z, an0);
                an1 = bffma2(aN[4 * k + 3], h.w, an1);
            }
        }

        // ---- segment B: peer 64 cols, all-register weights ----
        mbar_wait(mbarP, par);
        {
            const uint4* hB = (const uint4*)(h_raw + cur * HBUF_STRIDE + blkB * 144);
#pragma unroll
            for (int k = 0; k < 8; k++) {
                uint4 h = hB[k];
                ar0 = bffma2(bR[4 * k + 0], h.x, ar0);
                ar1 = bffma2(bR[4 * k + 1], h.y, ar1);
                az0 = bffma2(bZ[4 * k + 0], h.x, az0);
                az1 = bffma2(bZ[4 * k + 1], h.y, az1);
                an0 = bffma2(bN[4 * k + 0], h.x, an0);
                an1 = bffma2(bN[4 * k + 1], h.y, an1);
                ar0 = bffma2(bR[4 * k + 2], h.z, ar0);
                ar1 = bffma2(bR[4 * k + 3], h.w, ar1);
                az0 = bffma2(bZ[4 * k + 2], h.z, az0);
                az1 = bffma2(bZ[4 * k + 3], h.w, az1);
                an0 = bffma2(bN[4 * k + 2], h.z, an0);
                an1 = bffma2(bN[4 * k + 3], h.w, an1);
            }
        }

        float sr = (bflo(ar0) + bfhi(ar0)) + (bflo(ar1) + bfhi(ar1));
        float sz = (bflo(az0) + bfhi(az0)) + (bflo(az1) + bfhi(az1));
        float sn = (bflo(an0) + bfhi(an0)) + (bflo(an1) + bfhi(an1)) + bhn2;

        // 2-way reduce across the s pair
        sr += __shfl_xor_sync(0xffffffffu, sr, 1);
        sz += __shfl_xor_sync(0xffffffffu, sz, 1);
        sn += __shfl_xor_sync(0xffffffffu, sn, 1);

        // ---- epilogue (both s threads redundantly; s==0 stores) ----
        float r  = sigapx(gir + sr);
        float z  = sigapx(giz + sz);
        float n  = tanhapx(fmaf(r, sn, gin));
        float hn = fmaf(z, hreg - n, n);        // (1-z)*n + z*h
        hreg = hn;

        if (s == 0) {
            __nv_bfloat16 hb = __float2bfloat16(hn);
            unsigned short hb16 = *(unsigned short*)&hb;
            char* dstp = h_raw + nxt * HBUF_STRIDE + hoff;
            unsigned dst = smem_u32(dstp);
            // remote first: start the fabric latency as early as possible
            asm volatile(
                "{ .reg .u32 ra; mapa.shared::cluster.u32 ra, %0, %1;"
                "  st.shared::cluster.u16 [ra], %2; }"
                :: "r"(dst), "r"(peer), "h"(hb16) : "memory");
            asm volatile(
                "{ .reg .u32 ra; mapa.shared::cluster.u32 ra, %0, %1;"
                "  mbarrier.arrive.release.cluster.shared::cluster.b64 _, [ra]; }"
                :: "r"(mbarP), "r"(peer) : "memory");
            *(__nv_bfloat16*)dstp = hb;          // local store
            asm volatile("mbarrier.arrive.release.cta.shared::cta.b64 _, [%0];"
                         :: "r"(mbarL) : "memory");
        }
        gir = girn + bhr;
        giz = gizn + bhz;
        gin = ginn;
    }

    // sync final stores (phase of step SEQT has parity 0)
    mbar_wait(mbarL, 0u);
    mbar_wait(mbarP, 0u);

    // ---- final FC + sigmoid: final h lives in buffer 0 (2048 even) ----
    if (rank == 0 && tid < 64) {
        const int o = tid >> 5;
        const int lane = tid & 31;
        float sacc = 0.f;
#pragma unroll
        for (int i = 0; i < 8; i++) {
            int k = lane * 8 + i;
            const __nv_bfloat16* hp =
                (const __nv_bfloat16*)(h_raw + (k >> 6) * 144 + (k & 63) * 2);
            sacc = fmaf(__bfloat162float(*hp), W_fc[o * HIDN + k], sacc);
        }
#pragma unroll
        for (int off = 16; off; off >>= 1)
            sacc += __shfl_xor_sync(0xffffffffu, sacc, off);
        if (lane == 0) out[b * 2 + o] = __fdividef(1.f, 1.f + __expf(-(sacc + b_fc[o])));
    }
}

// ---------------------------------------------------------------------------
// launch
// ---------------------------------------------------------------------------
extern "C" void kernel_launch(void* const* d_in, const int* in_sizes, int n_in,
                              void* d_out, int out_size)
{
    const int*   tokens = (const int*)  d_in[0];
    const float* emb    = (const float*)d_in[1];
    const float* W_ih   = (const float*)d_in[2];
    const float* W_hh   = (const float*)d_in[3];
    const float* b_ih   = (const float*)d_in[4];
    const float* b_hh   = (const float*)d_in[5];
    const float* W_fc   = (const float*)d_in[6];
    const float* b_fc   = (const float*)d_in[7];
    float* out = (float*)d_out;

    cudaFuncSetAttribute(eprime_tc_kernel,
                         cudaFuncAttributeMaxDynamicSharedMemorySize, EPR_SMEM);
    cudaFuncSetAttribute(scan_kernel,
                         cudaFuncAttributeMaxDynamicSharedMemorySize, SCAN_SMEM);

    eprime_tc_kernel<<<(VOCABN + 127) / 128, 256, EPR_SMEM>>>(emb, W_ih, b_ih);

    scan_kernel<<<2 * NBATCH, 256, SCAN_SMEM>>>(tokens, W_hh, b_hh, W_fc, b_fc, out);

    (void)in_sizes; (void)n_in; (void)out_size;
}

// round 14
// speedup vs baseline: 2.2437x; 1.0402x over previous
#include <cuda_runtime.h>
#include <cuda_bf16.h>
#include <cstdint>
#include <cstddef>

#define VOCABN 50257
#define EMBN   256
#define HIDN   256
#define NBATCH 64
#define SEQT   2048
#define G3     768

// 154 MB scratch: E'[v][j] = emb[v] . W_ih[j] + b_ih[j]
__device__ float g_Ep[(size_t)VOCABN * G3];

// ---------------------------------------------------------------------------
// helpers
// ---------------------------------------------------------------------------
__device__ __forceinline__ float bflo(unsigned u) { return __uint_as_float(u << 16); }
__device__ __forceinline__ float bfhi(unsigned u) { return __uint_as_float(u & 0xffff0000u); }
__device__ __forceinline__ float tanhapx(float x) {
    float y;
    asm("tanh.approx.f32 %0, %1;" : "=f"(y) : "f"(x));
    return y;
}
__device__ __forceinline__ float sigapx(float x) {   // 0.5 + 0.5*tanh(x/2)
    return fmaf(0.5f, tanhapx(0.5f * x), 0.5f);
}
__device__ __forceinline__ unsigned smem_u32(const void* p) {
    unsigned a;
    asm("{ .reg .u64 t; cvta.to.shared.u64 t, %1; cvt.u32.u64 %0, t; }" : "=r"(a) : "l"(p));
    return a;
}
__device__ __forceinline__ unsigned bffma2(unsigned a, unsigned b, unsigned c) {
    unsigned d;
    asm("fma.rn.bf16x2 %0, %1, %2, %3;" : "=r"(d) : "r"(a), "r"(b), "r"(c));
    return d;
}
__device__ __forceinline__ unsigned pack_bf2(float lo, float hi) {
    __nv_bfloat162 p = __floats2bfloat162_rn(lo, hi);
    return *(unsigned*)&p;
}
__device__ __forceinline__ void mbar_wait(unsigned mbar, unsigned parity) {
    asm volatile(
        "{\n\t.reg .pred P;\n\t"
        "WL_%=:\n\t"
        "mbarrier.try_wait.parity.acquire.cta.shared::cta.b64 P, [%0], %1, 0x989680;\n\t"
        "@P bra.uni WD_%=;\n\t"
        "bra.uni WL_%=;\n\t"
        "WD_%=:\n\t}"
        :: "r"(mbar), "r"(parity) : "memory");
}
__device__ __forceinline__ void mma16816(float* c,
    unsigned a0, unsigned a1, unsigned a2, unsigned a3,
    unsigned b0, unsigned b1)
{
    asm("mma.sync.aligned.m16n8k16.row.col.f32.bf16.bf16.f32 "
        "{%0,%1,%2,%3}, {%4,%5,%6,%7}, {%8,%9}, {%0,%1,%2,%3};"
        : "+f"(c[0]), "+f"(c[1]), "+f"(c[2]), "+f"(c[3])
        : "r"(a0), "r"(a1), "r"(a2), "r"(a3), "r"(b0), "r"(b1));
}

// ---------------------------------------------------------------------------
// Phase A: E' = emb @ W_ih^T + b_ih via bf16 mma.sync (unchanged from R11).
// ---------------------------------------------------------------------------
#define AW 132
#define EPR_SMEM ((128 + 64) * AW * 4)   // 101376 B

__global__ void __launch_bounds__(256) eprime_tc_kernel(
    const float* __restrict__ emb, const float* __restrict__ W_ih,
    const float* __restrict__ b_ih)
{
    extern __shared__ unsigned ts[];
    unsigned* sA = ts;                 // 128 x 132 words
    unsigned* sB = ts + 128 * AW;      // 64 x 132 words

    const int tid  = threadIdx.x;
    const int m0   = blockIdx.x * 128;
    const int warp = tid >> 5;
    const int lane = tid & 31;
    const int g    = lane >> 2;
    const int t    = lane & 3;
    const int mrow = warp * 16;

    for (int i = tid; i < 128 * 128; i += 256) {
        int r = i >> 7, w = i & 127;
        int gm = m0 + r; if (gm >= VOCABN) gm = VOCABN - 1;
        float2 f = *(const float2*)&emb[(size_t)gm * EMBN + w * 2];
        sA[r * AW + w] = pack_bf2(f.x, f.y);
    }

    for (int nb = 0; nb < 12; nb++) {
        __syncthreads();
        for (int i = tid; i < 64 * 128; i += 256) {
            int r = i >> 7, w = i & 127;
            float2 f = *(const float2*)&W_ih[(size_t)(nb * 64 + r) * EMBN + w * 2];
            sB[r * AW + w] = pack_bf2(f.x, f.y);
        }
        __syncthreads();

        float acc[8][4];
#pragma unroll
        for (int nf = 0; nf < 8; nf++)
#pragma unroll
            for (int j = 0; j < 4; j++) acc[nf][j] = 0.f;

#pragma unroll 4
        for (int ks = 0; ks < 16; ks++) {
            const int kw = ks * 8;
            unsigned a0 = sA[(mrow + g)     * AW + kw + t];
            unsigned a1 = sA[(mrow + g + 8) * AW + kw + t];
            unsigned a2 = sA[(mrow + g)     * AW + kw + 4 + t];
            unsigned a3 = sA[(mrow + g + 8) * AW + kw + 4 + t];
#pragma unroll
            for (int nf = 0; nf < 8; nf++) {
                unsigned b0 = sB[(nf * 8 + g) * AW + kw + t];
                unsigned b1 = sB[(nf * 8 + g) * AW + kw + 4 + t];
                mma16816(acc[nf], a0, a1, a2, a3, b0, b1);
            }
        }

#pragma unroll
        for (int nf = 0; nf < 8; nf++) {
            int n  = nb * 64 + nf * 8 + 2 * t;
            float bi0 = b_ih[n], bi1 = b_ih[n + 1];
            int r0 = m0 + mrow + g;
            int r1 = r0 + 8;
            if (r0 < VOCABN) {
                float2 v; v.x = acc[nf][0] + bi0; v.y = acc[nf][1] + bi1;
                *(float2*)&g_Ep[(size_t)r0 * G3 + n] = v;
            }
            if (r1 < VOCABN) {
                float2 v; v.x = acc[nf][2] + bi0; v.y = acc[nf][3] + bi1;
                *(float2*)&g_Ep[(size_t)r1 * G3 + n] = v;
            }
        }
    }
}

// ---------------------------------------------------------------------------
// Phase B: scan. Cluster of 2 CTAs per batch element, 256 FAT threads/CTA.
// Thread = (unit jj = tid>>1, split s = tid&1): 192 weight uints in regs.
// Sync protocol:
//  - local h coherence: __syncthreads (no local mbarrier)
//  - peer exchange: after BAR, warp 0 (tid<32) bulk-pushes the local 256 B
//    h region to the peer as 32 x 8 B st.shared::cluster, each followed by
//    that thread's own arrive.release.cluster on peer's mbarP (count 32).
//  Ordering: segB readers (t) -> BAR(t) -> push+arrive(t) -> peer waitP(t+1)
//  -> peer writes; local anti-deps all covered by the per-step BAR.
// ---------------------------------------------------------------------------
// smem layout (bytes):
//   [0,    1152)  h_bf   2 buffers x 4 blocks x 144 B (64 bf16 + 16 pad)
//   [1152, 9344)  tok_s  2048 int32
//   [9344, 9352)  mbarP
#define SCAN_SMEM 9352
#define HBUF_STRIDE 576   // bytes per h buffer (4 blocks x 144)

__global__ void __cluster_dims__(2, 1, 1) __launch_bounds__(256, 1) scan_kernel(
    const int* __restrict__ tokens, const float* __restrict__ W_hh,
    const float* __restrict__ b_hh, const float* __restrict__ W_fc,
    const float* __restrict__ b_fc, float* __restrict__ out)
{
    extern __shared__ char smem[];
    char* h_raw = smem;
    int*  tok_s = (int*)(smem + 1152);
    const unsigned mbarP = smem_u32(smem + 9344);

    const int tid = threadIdx.x;
    const int b   = blockIdx.x >> 1;
    unsigned rank;
    asm("mov.u32 %0, %%cluster_ctarank;" : "=r"(rank));
    const unsigned peer = rank ^ 1u;
    const int jj = tid >> 1;              // local hidden unit 0..127
    const int s  = tid & 1;               // column split within each half
    const int gj = (int)rank * 128 + jj;  // global hidden unit

    // ---- init: ALL weights in registers (6 x 32 uints) ----
    unsigned aR[32], aZ[32], aN[32];      // local segment
    unsigned bR[32], bZ[32], bN[32];      // peer segment
    {
        const float2* pr = (const float2*)(W_hh + (size_t)(gj)       * HIDN);
        const float2* pz = (const float2*)(W_hh + (size_t)(256 + gj) * HIDN);
        const float2* pn = (const float2*)(W_hh + (size_t)(512 + gj) * HIDN);
        const int la = (int)rank * 64 + s * 32;   // local float2 base
        const int pa = (int)peer * 64 + s * 32;   // peer float2 base
#pragma unroll
        for (int i = 0; i < 32; i++) {
            float2 f;
            f = pr[la + i]; aR[i] = pack_bf2(f.x, f.y);
            f = pr[pa + i]; bR[i] = pack_bf2(f.x, f.y);
            f = pz[la + i]; aZ[i] = pack_bf2(f.x, f.y);
            f = pz[pa + i]; bZ[i] = pack_bf2(f.x, f.y);
            f = pn[la + i]; aN[i] = pack_bf2(f.x, f.y);
            f = pn[pa + i]; bN[i] = pack_bf2(f.x, f.y);
        }
    }
    const float bhr = b_hh[gj];
    const float bhz = b_hh[256 + gj];
    const float bhn2 = 0.5f * b_hh[512 + gj];

    for (int i = tid; i < SEQT; i += 256) tok_s[i] = tokens[b * SEQT + i];
    for (int i = tid; i < 2 * HBUF_STRIDE / 4; i += 256) ((unsigned*)h_raw)[i] = 0u;
    if (tid == 0) {
        asm volatile("mbarrier.init.shared.b64 [%0], %1;" :: "r"(mbarP), "r"(32u) : "memory");
    }
    __syncthreads();
    asm volatile("barrier.cluster.arrive.aligned;" ::: "memory");
    asm volatile("barrier.cluster.wait.aligned;"  ::: "memory");

    // prime phase 0 of peer's mbarP (h(0) already zeroed on both sides)
    if (tid < 32) {
        asm volatile(
            "{ .reg .u32 ra; mapa.shared::cluster.u32 ra, %0, %1;"
            "  mbarrier.arrive.release.cluster.shared::cluster.b64 _, [ra]; }"
            :: "r"(mbarP), "r"(peer) : "memory");
    }

    const int blkA = (int)rank * 2 + s;           // local-segment h block
    const int blkB = (int)peer * 2 + s;           // peer-segment h block
    const int hoff = (gj >> 6) * 144 + (gj & 63) * 2;  // writer's h slot
    // pusher (tid<32): 8 B slice of the local 2-block region
    const int poff = (int)rank * 288 + ((tid >> 4) & 1) * 144 + (tid & 15) * 8;
    float hreg = 0.f;

    const float* ep0 = &g_Ep[(size_t)tok_s[0] * G3];
    float gir = __ldg(ep0 + gj)       + bhr;
    float giz = __ldg(ep0 + 256 + gj) + bhz;
    float gin = __ldg(ep0 + 512 + gj);

    for (int t = 0; t < SEQT; t++) {
        const int cur = t & 1;
        const int nxt = cur ^ 1;
        const unsigned par = (unsigned)(t & 1);

        // prefetch next step's preactivations (independent of h)
        const int tn = (t + 1 < SEQT) ? tok_s[t + 1] : tok_s[t];
        const float* epn = &g_Ep[(size_t)tn * G3];
        float girn = __ldg(epn + gj);
        float gizn = __ldg(epn + 256 + gj);
        float ginn = __ldg(epn + 512 + gj);

        unsigned ar0 = 0u, ar1 = 0u, az0 = 0u, az1 = 0u, an0 = 0u, an1 = 0u;

        // ---- segment A: local 64 cols (gated by previous step's BAR) ----
        {
            const uint4* hA = (const uint4*)(h_raw + cur * HBUF_STRIDE + blkA * 144);
#pragma unroll
            for (int k = 0; k < 8; k++) {
                uint4 h = hA[k];
                ar0 = bffma2(aR[4 * k + 0], h.x, ar0);
                ar1 = bffma2(aR[4 * k + 1], h.y, ar1);
                az0 = bffma2(aZ[4 * k + 0], h.x, az0);
                az1 = bffma2(aZ[4 * k + 1], h.y, az1);
                an0 = bffma2(aN[4 * k + 0], h.x, an0);
                an1 = bffma2(aN[4 * k + 1], h.y, an1);
                ar0 = bffma2(aR[4 * k + 2], h.z, ar0);
                ar1 = bffma2(aR[4 * k + 3], h.w, ar1);
                az0 = bffma2(aZ[4 * k + 2], h.z, az0);
                az1 = bffma2(aZ[4 * k + 3], h.w, az1);
                an0 = bffma2(aN[4 * k + 2], h.z, an0);
                an1 = bffma2(aN[4 * k + 3], h.w, an1);
            }
        }

        // ---- segment B: peer 64 cols (gated by peer's bulk push) ----
        mbar_wait(mbarP, par);
        {
            const uint4* hB = (const uint4*)(h_raw + cur * HBUF_STRIDE + blkB * 144);
#pragma unroll
            for (int k = 0; k < 8; k++) {
                uint4 h = hB[k];
                ar0 = bffma2(bR[4 * k + 0], h.x, ar0);
                ar1 = bffma2(bR[4 * k + 1], h.y, ar1);
                az0 = bffma2(bZ[4 * k + 0], h.x, az0);
                az1 = bffma2(bZ[4 * k + 1], h.y, az1);
                an0 = bffma2(bN[4 * k + 0], h.x, an0);
                an1 = bffma2(bN[4 * k + 1], h.y, an1);
                ar0 = bffma2(bR[4 * k + 2], h.z, ar0);
                ar1 = bffma2(bR[4 * k + 3], h.w, ar1);
                az0 = bffma2(bZ[4 * k + 2], h.z, az0);
                az1 = bffma2(bZ[4 * k + 3], h.w, az1);
                an0 = bffma2(bN[4 * k + 2], h.z, an0);
                an1 = bffma2(bN[4 * k + 3], h.w, an1);
            }
        }

        float sr = (bflo(ar0) + bfhi(ar0)) + (bflo(ar1) + bfhi(ar1));
        float sz = (bflo(az0) + bfhi(az0)) + (bflo(az1) + bfhi(az1));
        float sn = (bflo(an0) + bfhi(an0)) + (bflo(an1) + bfhi(an1)) + bhn2;

        // 2-way reduce across the s pair
        sr += __shfl_xor_sync(0xffffffffu, sr, 1);
        sz += __shfl_xor_sync(0xffffffffu, sz, 1);
        sn += __shfl_xor_sync(0xffffffffu, sn, 1);

        // ---- epilogue (both s threads redundantly; s==0 stores locally) ----
        float r  = sigapx(gir + sr);
        float z  = sigapx(giz + sz);
        float n  = tanhapx(fmaf(r, sn, gin));
        float hn = fmaf(z, hreg - n, n);        // (1-z)*n + z*h
        hreg = hn;

        if (s == 0) {
            *(__nv_bfloat16*)(h_raw + nxt * HBUF_STRIDE + hoff) = __float2bfloat16(hn);
        }
        __syncthreads();   // orders local h stores; gates next segA; drains STS

        // ---- bulk push: warp 0 sends the local 256 B h region to the peer ----
        if (tid < 32) {
            const unsigned srcp = smem_u32(h_raw + nxt * HBUF_STRIDE + poff);
            unsigned long long v;
            asm volatile("ld.shared.b64 %0, [%1];" : "=l"(v) : "r"(srcp));
            asm volatile(
                "{ .reg .u32 ra; mapa.shared::cluster.u32 ra, %0, %1;"
                "  st.shared::cluster.b64 [ra], %2; }"
                :: "r"(srcp), "r"(peer), "l"(v) : "memory");
            asm volatile(
                "{ .reg .u32 ra; mapa.shared::cluster.u32 ra, %0, %1;"
                "  mbarrier.arrive.release.cluster.shared::cluster.b64 _, [ra]; }"
                :: "r"(mbarP), "r"(peer) : "memory");
        }

        gir = girn + bhr;
        giz = gizn + bhz;
        gin = ginn;
    }

    // wait for the final push (step 2047's arrivals complete phase parity 0)
    mbar_wait(mbarP, 0u);

    // ---- final FC + sigmoid: final h lives in buffer 0 (2048 even) ----
    if (rank == 0 && tid < 64) {
        const int o = tid >> 5;
        const int lane = tid & 31;
        float sacc = 0.f;
#pragma unroll
        for (int i = 0; i < 8; i++) {
            int k = lane * 8 + i;
            const __nv_bfloat16* hp =
                (const __nv_bfloat16*)(h_raw + (k >> 6) * 144 + (k & 63) * 2);
            sacc = fmaf(__bfloat162float(*hp), W_fc[o * HIDN + k], sacc);
        }
#pragma unroll
        for (int off = 16; off; off >>= 1)
            sacc += __shfl_xor_sync(0xffffffffu, sacc, off);
        if (lane == 0) out[b * 2 + o] = __fdividef(1.f, 1.f + __expf(-(sacc + b_fc[o])));
    }
}

// ---------------------------------------------------------------------------
// launch
// ---------------------------------------------------------------------------
extern "C" void kernel_launch(void* const* d_in, const int* in_sizes, int n_in,
                              void* d_out, int out_size)
{
    const int*   tokens = (const int*)  d_in[0];
    const float* emb    = (const float*)d_in[1];
    const float* W_ih   = (const float*)d_in[2];
    const float* W_hh   = (const float*)d_in[3];
    const float* b_ih   = (const float*)d_in[4];
    const float* b_hh   = (const float*)d_in[5];
    const float* W_fc   = (const float*)d_in[6];
    const float* b_fc   = (const float*)d_in[7];
    float* out = (float*)d_out;

    cudaFuncSetAttribute(eprime_tc_kernel,
                         cudaFuncAttributeMaxDynamicSharedMemorySize, EPR_SMEM);
    cudaFuncSetAttribute(scan_kernel,
                         cudaFuncAttributeMaxDynamicSharedMemorySize, SCAN_SMEM);

    eprime_tc_kernel<<<(VOCABN + 127) / 128, 256, EPR_SMEM>>>(emb, W_ih, b_ih);

    scan_kernel<<<2 * NBATCH, 256, SCAN_SMEM>>>(tokens, W_hh, b_hh, W_fc, b_fc, out);

    (void)in_sizes; (void)n_in; (void)out_size;
}